// round 8
// baseline (speedup 1.0000x reference)
#include <cuda_runtime.h>
#include <cstdint>

#define DD 256
#define NA_MAX (64*256)
#define NR_MAX (512*256)

// ---------------- scratch state (device globals; no allocation) ----------------
__device__ __align__(16) float gA [NA_MAX*DD];
__device__ __align__(16) float gR [NR_MAX*DD];
__device__ __align__(16) float gAq[NA_MAX*DD];
__device__ __align__(16) float gAk[NA_MAX*DD];
__device__ __align__(16) float gAv[NA_MAX*DD];
__device__ __align__(16) float gRq[NR_MAX*DD];
__device__ __align__(16) float gRk[NR_MAX*DD];
__device__ __align__(16) float gRv[NR_MAX*DD];
__device__ __align__(16) float gTA[NA_MAX*DD];
__device__ __align__(16) float gTR[NR_MAX*DD];
__device__ __align__(16) float gWp [10*DD*DD*2];  // weights: fragment-major hi/lo (3x path)
__device__ __align__(16) float gWp1[10*DD*DD];    // weights: fragment-major hi only (1x path)
__device__ float gInvA[NA_MAX];
__device__ float gInvR[NR_MAX];

__device__ __forceinline__ float leaky_f(float x) { return x >= 0.f ? x : 0.1f * x; }
__device__ __forceinline__ float sigmoid_f(float x) {
    return __fdividef(1.f, 1.f + __expf(-x));
}
__device__ __forceinline__ float to_tf32(float x) {
    uint32_t u;
    asm("cvt.rna.tf32.f32 %0, %1;" : "=r"(u) : "f"(x));
    return __uint_as_float(u);
}
__device__ __forceinline__ void split_tf32(float x, float& hi, float& lo) {
    uint32_t u;
    asm("cvt.rna.tf32.f32 %0, %1;" : "=r"(u) : "f"(x));
    hi = __uint_as_float(u);
    float r = x - hi;
    uint32_t v;
    asm("cvt.rna.tf32.f32 %0, %1;" : "=r"(v) : "f"(r));
    lo = __uint_as_float(v);
}
__device__ __forceinline__ void mma_tf32(float* d, const uint32_t* a, const uint32_t* b) {
    asm volatile(
        "mma.sync.aligned.m16n8k8.row.col.f32.tf32.tf32.f32 "
        "{%0,%1,%2,%3}, {%4,%5,%6,%7}, {%8,%9}, {%0,%1,%2,%3};\n"
        : "+f"(d[0]), "+f"(d[1]), "+f"(d[2]), "+f"(d[3])
        : "r"(a[0]), "r"(a[1]), "r"(a[2]), "r"(a[3]), "r"(b[0]), "r"(b[1]));
}
__device__ __forceinline__ uint32_t smem_u32(const void* p) {
    return (uint32_t)__cvta_generic_to_shared(p);
}
__device__ __forceinline__ void cp16(uint32_t s, const void* g) {
    asm volatile("cp.async.cg.shared.global [%0], [%1], 16;\n" :: "r"(s), "l"(g));
}
__device__ __forceinline__ void cp_commit() { asm volatile("cp.async.commit_group;\n"); }
template <int N> __device__ __forceinline__ void cp_wait() {
    asm volatile("cp.async.wait_group %0;\n" :: "n"(N));
}

// ---------------- per-row 1/count scales ----------------
__global__ void fill_inv_kernel(const int* __restrict__ lig, const int* __restrict__ res) {
    int b = blockIdx.x;
    int as = lig[2*b], ac = lig[2*b+1];
    int rs = res[2*b], rc = res[2*b+1];
    float ia = 1.f / (float)rc;
    float ir = 1.f / (float)ac;
    for (int i = threadIdx.x; i < ac; i += blockDim.x) gInvA[as + i] = ia;
    for (int i = threadIdx.x; i < rc; i += blockDim.x) gInvR[rs + i] = ir;
}

// ---------------- weight presplit + permute (fragment-major) ----------------
// 3x layout per (slot,coltile,ktile): 4096-float chunk  ((kk*8+nf8)*32+lane)*4 + {bh0,bh1,bl0,bl1}
// 1x layout per (slot,coltile,ktile): 2048-float chunk  ((kk*8+nf8)*32+lane)*2 + {bh0,bh1}
struct WIn { const float* w[10]; };
__global__ void presplit_w_kernel(WIn win, float* __restrict__ wp, float* __restrict__ wp1) {
    int i = blockIdx.x * 256 + threadIdx.x;
    if (i >= 10 * DD * DD) return;
    int s = i >> 16, rem = i & 65535;
    int k = rem >> 8, n = rem & 255;
    float h, l;
    split_tf32(win.w[s][rem], h, l);
    int coltile = n >> 6, nf8 = (n >> 3) & 7, lq = n & 7;
    int ktile = k >> 5, kk = (k >> 3) & 3, lr = k & 3, khalf = (k >> 2) & 1;
    int lane = lq * 4 + lr;
    int chunk = (s * 4 + coltile) * 8 + ktile;
    int fr = (kk * 8 + nf8) * 32 + lane;
    size_t b3 = (size_t)chunk * 4096 + (size_t)fr * 4;
    wp[b3 + khalf] = h;
    wp[b3 + 2 + khalf] = l;
    size_t b1 = (size_t)chunk * 2048 + (size_t)fr * 2;
    wp1[b1 + khalf] = h;
}

// ---------------- fused tf32 pipelined GEMM (PREC 1|3, NT coltiles/CTA, 3-stage) ----------------
// grid = (NW * 4/NT, aTiles+rTiles). X raw row-major, W pre-split fragment-major.
// MODE 0: C = XW ; 1: C = leaky(XW) ; 2: C = leaky(XW)*scale[r] + base[r,c]
struct GArgs {
    const float* X[2];
    const float* Wp[2][3];     // slot bases (gWp for PREC=3, gWp1 for PREC=1)
    float*       C[2][3];
    const float* scale[2];
    const float* base[2];
    int M[2];
    int aTiles;
};

#define GX_STR 36
#define GA_FLOATS (128*GX_STR)             // 4608
#define GEMM_SMEM (3*(GA_FLOATS + 4096)*4) // 104448 B (both PREC1/NT2 and PREC3/NT1)

template <int BKT1, int NT>
__device__ __forceinline__ void gemm_stage(const float* X, const float* Wb,
                                           float* sXb, float* sBb,
                                           int row0, int M, int t, int tid)
{
    const int k0 = t * 32;
    #pragma unroll
    for (int j = 0; j < 4; j++) {
        int idx = tid + 256 * j;
        int row = idx >> 3, ch = idx & 7;
        int grow = row0 + row; if (grow > M - 1) grow = M - 1;   // clamp: garbage rows never stored
        cp16(smem_u32(sXb + row * GX_STR + ch * 4), X + (size_t)grow * DD + k0 + ch * 4);
    }
    #pragma unroll
    for (int ct = 0; ct < NT; ct++) {
        const float* src = Wb + (size_t)(ct * 8 + t) * BKT1;
        #pragma unroll
        for (int j = 0; j < BKT1 / 1024; j++)
            cp16(smem_u32(sBb + ct * BKT1 + (tid + 256 * j) * 4), src + (size_t)(tid + 256 * j) * 4);
    }
}

template <int MODE, int PREC, int NT>
__global__ void __launch_bounds__(256, 2) gemm_fused_kernel(GArgs g)
{
    constexpr int BKT1 = (PREC == 3) ? 4096 : 2048;
    constexpr int BKT = NT * BKT1;
    constexpr int STAGE = GA_FLOATS + BKT;
    constexpr int NF = 4 * NT;
    constexpr int CGRP = 4 / NT;
    extern __shared__ float smf[];

    const int side = (blockIdx.y >= g.aTiles) ? 1 : 0;
    const int rt = side ? blockIdx.y - g.aTiles : blockIdx.y;
    const int w = blockIdx.x / CGRP;
    const int cg = blockIdx.x % CGRP;
    const int col0 = cg * (64 * NT);
    const int M = g.M[side];
    const int row0 = rt * 128;

    const float* X = g.X[side];
    const float* Wb = g.Wp[side][w] + (size_t)(cg * NT) * (8 * BKT1);
    float* C = g.C[side][w];

    const int tid = threadIdx.x, lane = tid & 31, warp = tid >> 5;
    const int wm = warp >> 1, wn = warp & 1;
    const int lq = lane >> 2, lr = lane & 3;

    float* sX[3] = { smf, smf + STAGE, smf + 2 * STAGE };
    float* sB[3] = { smf + GA_FLOATS, smf + STAGE + GA_FLOATS, smf + 2 * STAGE + GA_FLOATS };

    float acc[2][NF][4] = {};

    gemm_stage<BKT1, NT>(X, Wb, sX[0], sB[0], row0, M, 0, tid);
    cp_commit();
    gemm_stage<BKT1, NT>(X, Wb, sX[1], sB[1], row0, M, 1, tid);
    cp_commit();

    for (int t = 0; t < 8; t++) {
        int buf = t % 3;
        if (t < 6) {
            gemm_stage<BKT1, NT>(X, Wb, sX[(t + 2) % 3], sB[(t + 2) % 3], row0, M, t + 2, tid);
            cp_commit();
            cp_wait<2>();
        } else {
            cp_wait<0>();
        }
        __syncthreads();

        #pragma unroll
        for (int kk = 0; kk < 4; kk++) {
            uint32_t ah[2][4], al[2][4];
            #pragma unroll
            for (int mf = 0; mf < 2; mf++) {
                const float* xb = sX[buf] + (wm * 32 + mf * 16 + lq) * GX_STR + kk * 8 + lr;
                float raw[4];
                raw[0] = xb[0]; raw[1] = xb[8 * GX_STR];
                raw[2] = xb[4]; raw[3] = xb[8 * GX_STR + 4];
                #pragma unroll
                for (int e = 0; e < 4; e++) {
                    if (PREC == 3) {
                        float h, l;
                        split_tf32(raw[e], h, l);
                        ah[mf][e] = __float_as_uint(h);
                        al[mf][e] = __float_as_uint(l);
                    } else {
                        ah[mf][e] = __float_as_uint(to_tf32(raw[e]));
                    }
                }
            }
            #pragma unroll
            for (int nf = 0; nf < NF; nf++) {
                const int ct = nf >> 2, nfi = nf & 3;
                if (PREC == 3) {
                    float4 bv = *(const float4*)(sB[buf] + ct * BKT1
                                 + (size_t)((kk * 8 + wn * 4 + nfi) * 32 + lane) * 4);
                    const uint32_t* bq = (const uint32_t*)&bv;
                    uint32_t bh[2] = { bq[0], bq[1] };
                    uint32_t bl[2] = { bq[2], bq[3] };
                    #pragma unroll
                    for (int mf = 0; mf < 2; mf++) {
                        mma_tf32(acc[mf][nf], al[mf], bh);
                        mma_tf32(acc[mf][nf], ah[mf], bl);
                        mma_tf32(acc[mf][nf], ah[mf], bh);
                    }
                } else {
                    float2 bv = *(const float2*)(sB[buf] + ct * BKT1
                                 + (size_t)((kk * 8 + wn * 4 + nfi) * 32 + lane) * 2);
                    uint32_t bh[2] = { __float_as_uint(bv.x), __float_as_uint(bv.y) };
                    #pragma unroll
                    for (int mf = 0; mf < 2; mf++)
                        mma_tf32(acc[mf][nf], ah[mf], bh);
                }
            }
        }
        __syncthreads();
    }

    // ---- epilogue ----
    #pragma unroll
    for (int mf = 0; mf < 2; mf++) {
        #pragma unroll
        for (int i = 0; i < 4; i++) {
            int r = row0 + wm * 32 + mf * 16 + lq + ((i >= 2) ? 8 : 0);
            if (r >= M) continue;
            float sc = (MODE == 2) ? g.scale[side][r] : 0.f;
            #pragma unroll
            for (int nf = 0; nf < NF; nf++) {
                int c = col0 + (nf >> 2) * 64 + wn * 32 + (nf & 3) * 8 + lr * 2 + (i & 1);
                float v = acc[mf][nf][i];
                if (MODE == 1) v = leaky_f(v);
                if (MODE == 2) v = leaky_f(v) * sc + g.base[side][(size_t)r * DD + c];
                C[(size_t)r * DD + c] = v;
            }
        }
    }
}

// ---------------- mma sigmoid attention, cp.async pipelined, permuted Q ----------------
#define KV_STR 264
#define SSTR2 40
#define ATT_QP 0
#define ATT_SS 16384
#define ATT_RA (16384 + 64*SSTR2)
#define ATT_RB (ATT_RA + 2*32*KV_STR)
#define ATT_SMEM ((ATT_RB + 2*32*KV_STR) * 4)   // 210944 B

__device__ __forceinline__ void attn_stage_kv(const float* K, const float* V,
                                              float* regKb, float* regVb,
                                              size_t kv0, int t0, int kvc, int tid)
{
    #pragma unroll
    for (int i = 0; i < 8; i++) {
        int idx = tid + 256 * i;
        int row = idx >> 6, ch = idx & 63;
        int gr = t0 + row; if (gr > kvc - 1) gr = kvc - 1;   // clamp: masked later
        cp16(smem_u32(regKb + row * KV_STR + ch * 4), K + (kv0 + gr) * DD + ch * 4);
        cp16(smem_u32(regVb + row * KV_STR + ch * 4), V + (kv0 + gr) * DD + ch * 4);
    }
}

__global__ void attn_mma_kernel(const float* __restrict__ Q, const float* __restrict__ K,
                                const float* __restrict__ V, float* __restrict__ O,
                                const int* __restrict__ scQ, const int* __restrict__ scKV)
{
    extern __shared__ float smf[];
    float* Qp = smf + ATT_QP;
    float* sS = smf + ATT_SS;
    float* regK[2]; float* regV[2];
    regK[0] = smf + ATT_RA; regV[0] = regK[0] + 32 * KV_STR;
    regK[1] = smf + ATT_RB; regV[1] = regK[1] + 32 * KV_STR;
    float* Qraw = regK[0];

    const int b = blockIdx.x;
    const int qs0 = scQ[2*b], qc = scQ[2*b+1];
    const int kv0i = scKV[2*b], kvc = scKV[2*b+1];
    const int qbeg = blockIdx.y * 64;
    if (qbeg >= qc) return;
    const int qcnt = (qc - qbeg < 64) ? (qc - qbeg) : 64;

    const int tid = threadIdx.x, lane = tid & 31, warp = tid >> 5;
    const int lq = lane >> 2, lr = lane & 3;

    #pragma unroll
    for (int i = 0; i < 16; i++) {
        int idx = tid + 256 * i;
        int row = idx >> 6, ch = idx & 63;
        int gr = qbeg + row; if (gr > qc - 1) gr = qc - 1;
        cp16(smem_u32(Qraw + row * KV_STR + ch * 4), Q + (size_t)(qs0 + gr) * DD + ch * 4);
    }
    cp_commit();
    attn_stage_kv(K, V, regK[1], regV[1], (size_t)kv0i, 0, kvc, tid);
    cp_commit();

    cp_wait<1>();
    __syncthreads();

    {
        int mt = warp >> 1;
        #pragma unroll
        for (int i = 0; i < 16; i++) {
            int kk = (warp & 1) * 16 + i;
            const float* qb = Qraw + (mt * 16 + lq) * KV_STR + kk * 8 + lr;
            float4 v;
            v.x = to_tf32(qb[0]);
            v.y = to_tf32(qb[8 * KV_STR]);
            v.z = to_tf32(qb[4]);
            v.w = to_tf32(qb[8 * KV_STR + 4]);
            *(float4*)(Qp + ((size_t)(mt * 32 + kk) * 32 + lane) * 4) = v;
        }
    }
    __syncthreads();

    float o[4][4][4] = {};
    const int nT = (kvc + 31) >> 5;

    for (int t = 0; t < nT; t++) {
        int buf = (t & 1) ^ 1;
        if (t + 1 < nT) {
            attn_stage_kv(K, V, regK[buf ^ 1], regV[buf ^ 1], (size_t)kv0i, (t + 1) * 32, kvc, tid);
            cp_commit();
            cp_wait<1>();
        } else {
            cp_wait<0>();
        }
        __syncthreads();

        int klim = kvc - t * 32; if (klim > 32) klim = 32;

        {
            const int wm = warp >> 1, wn = warp & 1;
            const int m0 = wm * 16, n0 = wn * 16;
            float s[2][4] = {};
            #pragma unroll 4
            for (int kk = 0; kk < 32; kk++) {
                float4 qv = *(const float4*)(Qp + ((size_t)(wm * 32 + kk) * 32 + lane) * 4);
                uint32_t a[4] = { __float_as_uint(qv.x), __float_as_uint(qv.y),
                                  __float_as_uint(qv.z), __float_as_uint(qv.w) };
                uint32_t bb[2][2];
                #pragma unroll
                for (int nf = 0; nf < 2; nf++) {
                    const float* kp = regK[buf] + (n0 + nf * 8 + lq) * KV_STR + kk * 8 + lr;
                    bb[nf][0] = __float_as_uint(to_tf32(kp[0]));
                    bb[nf][1] = __float_as_uint(to_tf32(kp[4]));
                }
                mma_tf32(s[0], a, bb[0]);
                mma_tf32(s[1], a, bb[1]);
            }
            #pragma unroll
            for (int nf = 0; nf < 2; nf++)
                #pragma unroll
                for (int e = 0; e < 4; e++) {
                    int row = m0 + lq + ((e >= 2) ? 8 : 0);
                    int col = n0 + nf * 8 + lr * 2 + (e & 1);
                    float v = (col < klim) ? sigmoid_f(s[nf][e]) : 0.f;
                    sS[row * SSTR2 + col] = to_tf32(v);
                }
        }
        __syncthreads();

        {
            const int n0 = warp * 32;
            #pragma unroll
            for (int ks = 0; ks < 4; ks++) {
                uint32_t a[4][4], bb[4][2];
                #pragma unroll
                for (int mf = 0; mf < 4; mf++) {
                    const float* sp = sS + (mf * 16 + lq) * SSTR2 + ks * 8 + lr;
                    a[mf][0] = __float_as_uint(sp[0]);
                    a[mf][1] = __float_as_uint(sp[8 * SSTR2]);
                    a[mf][2] = __float_as_uint(sp[4]);
                    a[mf][3] = __float_as_uint(sp[8 * SSTR2 + 4]);
                }
                #pragma unroll
                for (int nf = 0; nf < 4; nf++) {
                    const float* vp = regV[buf] + (ks * 8 + lr) * KV_STR + n0 + nf * 8 + lq;
                    bb[nf][0] = __float_as_uint(to_tf32(vp[0]));
                    bb[nf][1] = __float_as_uint(to_tf32(vp[4 * KV_STR]));
                }
                #pragma unroll
                for (int mf = 0; mf < 4; mf++)
                    #pragma unroll
                    for (int nf = 0; nf < 4; nf++)
                        mma_tf32(o[mf][nf], a[mf], bb[nf]);
            }
        }
        __syncthreads();
    }

    const int n0 = warp * 32;
    float* Obase = O + (size_t)(qs0 + qbeg) * DD;
    #pragma unroll
    for (int mf = 0; mf < 4; mf++)
        #pragma unroll
        for (int e = 0; e < 4; e++) {
            int row = mf * 16 + lq + ((e >= 2) ? 8 : 0);
            if (row >= qcnt) continue;
            #pragma unroll
            for (int nf = 0; nf < 4; nf++) {
                int col = n0 + nf * 8 + lr * 2 + (e & 1);
                Obase[(size_t)row * DD + col] = o[mf][nf][e];
            }
        }
}

// ---------------- final output: concat(A_flat, R_flat) ----------------
__global__ void copy_out_kernel(float* __restrict__ out, int nA, int nR) {
    size_t na4 = (size_t)nA * DD / 4;
    size_t tot = (size_t)(nA + nR) * DD / 4;
    const float4* a4 = (const float4*)gA;
    const float4* r4 = (const float4*)gR;
    for (size_t i = blockIdx.x * (size_t)blockDim.x + threadIdx.x; i < tot;
         i += (size_t)gridDim.x * blockDim.x) {
        ((float4*)out)[i] = (i < na4) ? a4[i] : r4[i - na4];
    }
}

// ---------------- host launch ----------------
extern "C" void kernel_launch(void* const* d_in, const int* in_sizes, int n_in,
                              void* d_out, int out_size) {
    const float* fatoms = (const float*)d_in[0];
    const float* fres   = (const float*)d_in[1];
    const int* lig = (const int*)d_in[12];
    const int* res = (const int*)d_in[13];

    int nA = in_sizes[0] / DD;
    int nR = in_sizes[1] / DD;

    float *pA, *pR, *pAq, *pAk, *pAv, *pRq, *pRk, *pRv, *pTA, *pTR;
    float *pWp, *pWp1, *pInvA, *pInvR;
    cudaGetSymbolAddress((void**)&pA,  gA);
    cudaGetSymbolAddress((void**)&pR,  gR);
    cudaGetSymbolAddress((void**)&pAq, gAq);
    cudaGetSymbolAddress((void**)&pAk, gAk);
    cudaGetSymbolAddress((void**)&pAv, gAv);
    cudaGetSymbolAddress((void**)&pRq, gRq);
    cudaGetSymbolAddress((void**)&pRk, gRk);
    cudaGetSymbolAddress((void**)&pRv, gRv);
    cudaGetSymbolAddress((void**)&pTA, gTA);
    cudaGetSymbolAddress((void**)&pTR, gTR);
    cudaGetSymbolAddress((void**)&pWp, gWp);
    cudaGetSymbolAddress((void**)&pWp1, gWp1);
    cudaGetSymbolAddress((void**)&pInvA, gInvA);
    cudaGetSymbolAddress((void**)&pInvR, gInvR);

    cudaFuncSetAttribute(gemm_fused_kernel<1,3,1>, cudaFuncAttributeMaxDynamicSharedMemorySize, GEMM_SMEM);
    cudaFuncSetAttribute(gemm_fused_kernel<0,1,2>, cudaFuncAttributeMaxDynamicSharedMemorySize, GEMM_SMEM);
    cudaFuncSetAttribute(gemm_fused_kernel<2,1,2>, cudaFuncAttributeMaxDynamicSharedMemorySize, GEMM_SMEM);
    cudaFuncSetAttribute(attn_mma_kernel, cudaFuncAttributeMaxDynamicSharedMemorySize, ATT_SMEM);

    // weight slot order: 0=W_lig_t 1=WQl 2=WKl 3=WVl 4=WOl | 5=W_res_t 6=WQr 7=WKr 8=WVr 9=WOr
    WIn win;
    win.w[0] = (const float*)d_in[2];
    win.w[1] = (const float*)d_in[4];
    win.w[2] = (const float*)d_in[5];
    win.w[3] = (const float*)d_in[6];
    win.w[4] = (const float*)d_in[7];
    win.w[5] = (const float*)d_in[3];
    win.w[6] = (const float*)d_in[8];
    win.w[7] = (const float*)d_in[9];
    win.w[8] = (const float*)d_in[10];
    win.w[9] = (const float*)d_in[11];

    const int aTiles = (nA + 127) / 128;
    const int rTiles = (nR + 127) / 128;
    const int totTiles = aTiles + rTiles;
    const int WSLOT3 = DD * DD * 2;
    const int WSLOT1 = DD * DD;

    fill_inv_kernel<<<256, 256>>>(lig, res);
    presplit_w_kernel<<<(10 * DD * DD + 255) / 256, 256>>>(win, pWp, pWp1);

    // init transforms (3x): A0 = leaky(fatoms@W_lig_t), R0 = leaky(fres@W_res_t)
    GArgs gi = {};
    gi.X[0] = fatoms; gi.X[1] = fres;
    gi.Wp[0][0] = pWp + 0 * WSLOT3; gi.Wp[1][0] = pWp + 5 * WSLOT3;
    gi.C[0][0] = pA; gi.C[1][0] = pR;
    gi.M[0] = nA; gi.M[1] = nR; gi.aTiles = aTiles;

    // fused QKV projections (1x, N=128/CTA)
    GArgs gq = {};
    gq.X[0] = pA; gq.X[1] = pR;
    for (int j = 0; j < 3; j++) {
        gq.Wp[0][j] = pWp1 + (1 + j) * WSLOT1;
        gq.Wp[1][j] = pWp1 + (6 + j) * WSLOT1;
    }
    gq.C[0][0] = pAq; gq.C[0][1] = pAk; gq.C[0][2] = pAv;
    gq.C[1][0] = pRq; gq.C[1][1] = pRk; gq.C[1][2] = pRv;
    gq.M[0] = nA; gq.M[1] = nR; gq.aTiles = aTiles;

    // output GEMMs (1x, N=128/CTA): A = leaky(TA@WOl)*invA + A ; R = leaky(TR@WOr)*invR + R
    GArgs go = {};
    go.X[0] = pTA; go.X[1] = pTR;
    go.Wp[0][0] = pWp1 + 4 * WSLOT1; go.Wp[1][0] = pWp1 + 9 * WSLOT1;
    go.C[0][0] = pA; go.C[1][0] = pR;
    go.scale[0] = pInvA; go.scale[1] = pInvR;
    go.base[0] = pA; go.base[1] = pR;
    go.M[0] = nA; go.M[1] = nR; go.aTiles = aTiles;

    gemm_fused_kernel<1,3,1><<<dim3(4, totTiles), 256, GEMM_SMEM>>>(gi);

    for (int it = 0; it < 3; it++) {
        gemm_fused_kernel<0,1,2><<<dim3(6, totTiles), 256, GEMM_SMEM>>>(gq);

        // atoms attend to residues: Q=Aq (<=64 rows/complex), K/V = Rk/Rv
        attn_mma_kernel<<<dim3(256, 1), 256, ATT_SMEM>>>(pAq, pRk, pRv, pTA, lig, res);
        // residues attend to atoms: Q=Rq (64-row chunks), K/V = Ak/Av
        attn_mma_kernel<<<dim3(256, 8), 256, ATT_SMEM>>>(pRq, pAk, pAv, pTR, res, lig);

        gemm_fused_kernel<2,1,2><<<dim3(2, totTiles), 256, GEMM_SMEM>>>(go);
    }

    copy_out_kernel<<<1024, 256>>>((float*)d_out, nA, nR);
}

// round 9
// speedup vs baseline: 1.1334x; 1.1334x over previous
#include <cuda_runtime.h>
#include <cstdint>

#define DD 256
#define NA_MAX (64*256)
#define NR_MAX (512*256)

// ---------------- scratch state (device globals; no allocation) ----------------
__device__ __align__(16) float gA  [NA_MAX*DD];   // state raw fp32
__device__ __align__(16) float gR  [NR_MAX*DD];
__device__ __align__(16) float gAt [NA_MAX*DD];   // state tf32-rounded (GEMM X input)
__device__ __align__(16) float gRt [NR_MAX*DD];
__device__ __align__(16) float gAq[NA_MAX*DD];
__device__ __align__(16) float gAk[NA_MAX*DD];
__device__ __align__(16) float gAv[NA_MAX*DD];
__device__ __align__(16) float gRq[NR_MAX*DD];
__device__ __align__(16) float gRk[NR_MAX*DD];
__device__ __align__(16) float gRv[NR_MAX*DD];
__device__ __align__(16) float gTA[NA_MAX*DD];    // attn out, stored tf32-rounded
__device__ __align__(16) float gTR[NR_MAX*DD];
__device__ __align__(16) float gWp [10*DD*DD*2];  // weights: fragment-major hi/lo (3x path)
__device__ __align__(16) float gWp1[10*DD*DD];    // weights: fragment-major hi only (1x path)
__device__ float gInvA[NA_MAX];
__device__ float gInvR[NR_MAX];

__device__ __forceinline__ float leaky_f(float x) { return x >= 0.f ? x : 0.1f * x; }
__device__ __forceinline__ float sigmoid_f(float x) {
    return __fdividef(1.f, 1.f + __expf(-x));
}
__device__ __forceinline__ float to_tf32(float x) {
    uint32_t u;
    asm("cvt.rna.tf32.f32 %0, %1;" : "=r"(u) : "f"(x));
    return __uint_as_float(u);
}
__device__ __forceinline__ void split_tf32(float x, float& hi, float& lo) {
    uint32_t u;
    asm("cvt.rna.tf32.f32 %0, %1;" : "=r"(u) : "f"(x));
    hi = __uint_as_float(u);
    float r = x - hi;
    uint32_t v;
    asm("cvt.rna.tf32.f32 %0, %1;" : "=r"(v) : "f"(r));
    lo = __uint_as_float(v);
}
__device__ __forceinline__ void mma_tf32(float* d, const uint32_t* a, const uint32_t* b) {
    asm volatile(
        "mma.sync.aligned.m16n8k8.row.col.f32.tf32.tf32.f32 "
        "{%0,%1,%2,%3}, {%4,%5,%6,%7}, {%8,%9}, {%0,%1,%2,%3};\n"
        : "+f"(d[0]), "+f"(d[1]), "+f"(d[2]), "+f"(d[3])
        : "r"(a[0]), "r"(a[1]), "r"(a[2]), "r"(a[3]), "r"(b[0]), "r"(b[1]));
}
__device__ __forceinline__ void ldsm_x4(uint32_t* r, uint32_t a) {
    asm volatile("ldmatrix.sync.aligned.m8n8.x4.shared.b16 {%0,%1,%2,%3}, [%4];"
        : "=r"(r[0]), "=r"(r[1]), "=r"(r[2]), "=r"(r[3]) : "r"(a));
}
__device__ __forceinline__ uint32_t smem_u32(const void* p) {
    return (uint32_t)__cvta_generic_to_shared(p);
}
__device__ __forceinline__ void cp16(uint32_t s, const void* g) {
    asm volatile("cp.async.cg.shared.global [%0], [%1], 16;\n" :: "r"(s), "l"(g));
}
__device__ __forceinline__ void cp_commit() { asm volatile("cp.async.commit_group;\n"); }
template <int N> __device__ __forceinline__ void cp_wait() {
    asm volatile("cp.async.wait_group %0;\n" :: "n"(N));
}

// ---------------- per-row 1/count scales ----------------
__global__ void fill_inv_kernel(const int* __restrict__ lig, const int* __restrict__ res) {
    int b = blockIdx.x;
    int as = lig[2*b], ac = lig[2*b+1];
    int rs = res[2*b], rc = res[2*b+1];
    float ia = 1.f / (float)rc;
    float ir = 1.f / (float)ac;
    for (int i = threadIdx.x; i < ac; i += blockDim.x) gInvA[as + i] = ia;
    for (int i = threadIdx.x; i < rc; i += blockDim.x) gInvR[rs + i] = ir;
}

// ---------------- weight presplit + permute (fragment-major) ----------------
struct WIn { const float* w[10]; };
__global__ void presplit_w_kernel(WIn win, float* __restrict__ wp, float* __restrict__ wp1) {
    int i = blockIdx.x * 256 + threadIdx.x;
    if (i >= 10 * DD * DD) return;
    int s = i >> 16, rem = i & 65535;
    int k = rem >> 8, n = rem & 255;
    float h, l;
    split_tf32(win.w[s][rem], h, l);
    int coltile = n >> 6, nf8 = (n >> 3) & 7, lq = n & 7;
    int ktile = k >> 5, kk = (k >> 3) & 3, lr = k & 3, khalf = (k >> 2) & 1;
    int lane = lq * 4 + lr;
    int chunk = (s * 4 + coltile) * 8 + ktile;
    int fr = (kk * 8 + nf8) * 32 + lane;
    size_t b3 = (size_t)chunk * 4096 + (size_t)fr * 4;
    wp[b3 + khalf] = h;
    wp[b3 + 2 + khalf] = l;
    size_t b1 = (size_t)chunk * 2048 + (size_t)fr * 2;
    wp1[b1 + khalf] = h;
}

// ---------------- fused tf32 pipelined GEMM (PREC 1|3, 2-stage) ----------------
// grid = (NW*4, aTiles+rTiles). X row-major (PREC1: pre-rounded tf32), W fragment-major.
// MODE 0: C = XW ; 1: C = leaky(XW) ; 2: C = leaky(XW)*scale[r] + base[r,c]
// MODE 1/2 additionally store a tf32-rounded copy to Ct.
struct GArgs {
    const float* X[2];
    const float* Wp[2][3];
    float*       C[2][3];
    float*       Ct[2];        // rounded state out (MODE 1/2)
    const float* scale[2];
    const float* base[2];
    int M[2];
    int aTiles;
};

#define GX_STR 36
#define GA_FLOATS (128*GX_STR)             // 4608

template <int BKT>
__device__ __forceinline__ void gemm_stage(const float* X, const float* Wb,
                                           float* sXb, float* sBb,
                                           int row0, int M, int t, int tid)
{
    const int k0 = t * 32;
    #pragma unroll
    for (int j = 0; j < 4; j++) {
        int idx = tid + 256 * j;
        int row = idx >> 3, ch = idx & 7;
        int grow = row0 + row; if (grow > M - 1) grow = M - 1;   // clamp: garbage rows never stored
        cp16(smem_u32(sXb + row * GX_STR + ch * 4), X + (size_t)grow * DD + k0 + ch * 4);
    }
    const float* src = Wb + (size_t)t * BKT;
    #pragma unroll
    for (int j = 0; j < BKT / 1024; j++)
        cp16(smem_u32(sBb + (tid + 256 * j) * 4), src + (size_t)(tid + 256 * j) * 4);
}

template <int MODE, int PREC>
__global__ void __launch_bounds__(256, (PREC == 1) ? 3 : 2) gemm_fused_kernel(GArgs g)
{
    constexpr int BKT = (PREC == 3) ? 4096 : 2048;
    constexpr int STAGE = GA_FLOATS + BKT;
    extern __shared__ float smf[];

    const int side = (blockIdx.y >= g.aTiles) ? 1 : 0;
    const int rt = side ? blockIdx.y - g.aTiles : blockIdx.y;
    const int w = blockIdx.x >> 2, coltile = blockIdx.x & 3;
    const int col0 = coltile * 64;
    const int M = g.M[side];
    const int row0 = rt * 128;

    const float* X = g.X[side];
    const float* Wb = g.Wp[side][w] + (size_t)coltile * (8 * BKT);
    float* C = g.C[side][w];

    const int tid = threadIdx.x, lane = tid & 31, warp = tid >> 5;
    const int wm = warp >> 1, wn = warp & 1;
    const int lq = lane >> 2, lr = lane & 3;

    float* sX[2] = { smf,             smf + STAGE };
    float* sB[2] = { smf + GA_FLOATS, smf + STAGE + GA_FLOATS };

    float acc[2][4][4] = {};

    // ldmatrix address components (PREC1): group g of 8 lanes feeds matrix g
    const int grp = lane >> 3, rr8 = lane & 7;
    const int arow_off = (grp & 1) * 8 + rr8;        // + mf*16 + wm*32
    const int acol0 = (grp >> 1) * 4;

    gemm_stage<BKT>(X, Wb, sX[0], sB[0], row0, M, 0, tid);
    cp_commit();

    for (int t = 0; t < 8; t++) {
        int buf = t & 1;
        if (t < 7) {
            gemm_stage<BKT>(X, Wb, sX[buf ^ 1], sB[buf ^ 1], row0, M, t + 1, tid);
            cp_commit();
            cp_wait<1>();
        } else {
            cp_wait<0>();
        }
        __syncthreads();

        #pragma unroll
        for (int kk = 0; kk < 4; kk++) {
            uint32_t ah[2][4], al[2][4];
            if (PREC == 1) {
                #pragma unroll
                for (int mf = 0; mf < 2; mf++) {
                    uint32_t addr = smem_u32(sX[buf] + (wm * 32 + mf * 16 + arow_off) * GX_STR
                                             + kk * 8 + acol0);
                    ldsm_x4(ah[mf], addr);
                }
            } else {
                #pragma unroll
                for (int mf = 0; mf < 2; mf++) {
                    const float* xb = sX[buf] + (wm * 32 + mf * 16 + lq) * GX_STR + kk * 8 + lr;
                    float raw[4];
                    raw[0] = xb[0]; raw[1] = xb[8 * GX_STR];
                    raw[2] = xb[4]; raw[3] = xb[8 * GX_STR + 4];
                    #pragma unroll
                    for (int e = 0; e < 4; e++) {
                        float h, l;
                        split_tf32(raw[e], h, l);
                        ah[mf][e] = __float_as_uint(h);
                        al[mf][e] = __float_as_uint(l);
                    }
                }
            }
            #pragma unroll
            for (int nf = 0; nf < 4; nf++) {
                if (PREC == 3) {
                    float4 bv = *(const float4*)(sB[buf] + (size_t)((kk * 8 + wn * 4 + nf) * 32 + lane) * 4);
                    const uint32_t* bq = (const uint32_t*)&bv;
                    uint32_t bh[2] = { bq[0], bq[1] };
                    uint32_t bl[2] = { bq[2], bq[3] };
                    #pragma unroll
                    for (int mf = 0; mf < 2; mf++) {
                        mma_tf32(acc[mf][nf], al[mf], bh);
                        mma_tf32(acc[mf][nf], ah[mf], bl);
                        mma_tf32(acc[mf][nf], ah[mf], bh);
                    }
                } else {
                    float2 bv = *(const float2*)(sB[buf] + (size_t)((kk * 8 + wn * 4 + nf) * 32 + lane) * 2);
                    uint32_t bh[2] = { __float_as_uint(bv.x), __float_as_uint(bv.y) };
                    #pragma unroll
                    for (int mf = 0; mf < 2; mf++)
                        mma_tf32(acc[mf][nf], ah[mf], bh);
                }
            }
        }
        __syncthreads();
    }

    // ---- epilogue ----
    float* Ct = (MODE != 0) ? g.Ct[side] : nullptr;
    #pragma unroll
    for (int mf = 0; mf < 2; mf++) {
        #pragma unroll
        for (int i = 0; i < 4; i++) {
            int r = row0 + wm * 32 + mf * 16 + lq + ((i >= 2) ? 8 : 0);
            if (r >= M) continue;
            float sc = (MODE == 2) ? g.scale[side][r] : 0.f;
            #pragma unroll
            for (int nf = 0; nf < 4; nf++) {
                int c = col0 + wn * 32 + nf * 8 + lr * 2 + (i & 1);
                float v = acc[mf][nf][i];
                if (MODE == 1) v = leaky_f(v);
                if (MODE == 2) v = leaky_f(v) * sc + g.base[side][(size_t)r * DD + c];
                C[(size_t)r * DD + c] = v;
                if (MODE != 0) Ct[(size_t)r * DD + c] = to_tf32(v);
            }
        }
    }
}

#define GEMM_SMEM3 (2*(GA_FLOATS + 4096)*4)   // 69632 B
#define GEMM_SMEM1 (2*(GA_FLOATS + 2048)*4)   // 53248 B

// ---------------- mma sigmoid attention, cp.async pipelined, permuted Q ----------------
#define KV_STR 264
#define SSTR2 40
#define ATT_QP 0
#define ATT_SS 16384
#define ATT_RA (16384 + 64*SSTR2)
#define ATT_RB (ATT_RA + 2*32*KV_STR)
#define ATT_SMEM ((ATT_RB + 2*32*KV_STR) * 4)   // 210944 B

__device__ __forceinline__ void attn_stage_kv(const float* K, const float* V,
                                              float* regKb, float* regVb,
                                              size_t kv0, int t0, int kvc, int tid)
{
    #pragma unroll
    for (int i = 0; i < 8; i++) {
        int idx = tid + 256 * i;
        int row = idx >> 6, ch = idx & 63;
        int gr = t0 + row; if (gr > kvc - 1) gr = kvc - 1;   // clamp: masked later
        cp16(smem_u32(regKb + row * KV_STR + ch * 4), K + (kv0 + gr) * DD + ch * 4);
        cp16(smem_u32(regVb + row * KV_STR + ch * 4), V + (kv0 + gr) * DD + ch * 4);
    }
}

__global__ void attn_mma_kernel(const float* __restrict__ Q, const float* __restrict__ K,
                                const float* __restrict__ V, float* __restrict__ O,
                                const int* __restrict__ scQ, const int* __restrict__ scKV)
{
    extern __shared__ float smf[];
    float* Qp = smf + ATT_QP;
    float* sS = smf + ATT_SS;
    float* regK[2]; float* regV[2];
    regK[0] = smf + ATT_RA; regV[0] = regK[0] + 32 * KV_STR;
    regK[1] = smf + ATT_RB; regV[1] = regK[1] + 32 * KV_STR;
    float* Qraw = regK[0];

    const int b = blockIdx.x;
    const int qs0 = scQ[2*b], qc = scQ[2*b+1];
    const int kv0i = scKV[2*b], kvc = scKV[2*b+1];
    const int qbeg = blockIdx.y * 64;
    if (qbeg >= qc) return;
    const int qcnt = (qc - qbeg < 64) ? (qc - qbeg) : 64;

    const int tid = threadIdx.x, lane = tid & 31, warp = tid >> 5;
    const int lq = lane >> 2, lr = lane & 3;

    #pragma unroll
    for (int i = 0; i < 16; i++) {
        int idx = tid + 256 * i;
        int row = idx >> 6, ch = idx & 63;
        int gr = qbeg + row; if (gr > qc - 1) gr = qc - 1;
        cp16(smem_u32(Qraw + row * KV_STR + ch * 4), Q + (size_t)(qs0 + gr) * DD + ch * 4);
    }
    cp_commit();
    attn_stage_kv(K, V, regK[1], regV[1], (size_t)kv0i, 0, kvc, tid);
    cp_commit();

    cp_wait<1>();
    __syncthreads();

    {
        int mt = warp >> 1;
        #pragma unroll
        for (int i = 0; i < 16; i++) {
            int kk = (warp & 1) * 16 + i;
            const float* qb = Qraw + (mt * 16 + lq) * KV_STR + kk * 8 + lr;
            float4 v;
            v.x = to_tf32(qb[0]);
            v.y = to_tf32(qb[8 * KV_STR]);
            v.z = to_tf32(qb[4]);
            v.w = to_tf32(qb[8 * KV_STR + 4]);
            *(float4*)(Qp + ((size_t)(mt * 32 + kk) * 32 + lane) * 4) = v;
        }
    }
    __syncthreads();

    float o[4][4][4] = {};
    const int nT = (kvc + 31) >> 5;

    for (int t = 0; t < nT; t++) {
        int buf = (t & 1) ^ 1;
        if (t + 1 < nT) {
            attn_stage_kv(K, V, regK[buf ^ 1], regV[buf ^ 1], (size_t)kv0i, (t + 1) * 32, kvc, tid);
            cp_commit();
            cp_wait<1>();
        } else {
            cp_wait<0>();
        }
        __syncthreads();

        int klim = kvc - t * 32; if (klim > 32) klim = 32;

        {
            const int wm = warp >> 1, wn = warp & 1;
            const int m0 = wm * 16, n0 = wn * 16;
            float s[2][4] = {};
            #pragma unroll 4
            for (int kk = 0; kk < 32; kk++) {
                float4 qv = *(const float4*)(Qp + ((size_t)(wm * 32 + kk) * 32 + lane) * 4);
                uint32_t a[4] = { __float_as_uint(qv.x), __float_as_uint(qv.y),
                                  __float_as_uint(qv.z), __float_as_uint(qv.w) };
                uint32_t bb[2][2];
                #pragma unroll
                for (int nf = 0; nf < 2; nf++) {
                    const float* kp = regK[buf] + (n0 + nf * 8 + lq) * KV_STR + kk * 8 + lr;
                    bb[nf][0] = __float_as_uint(to_tf32(kp[0]));
                    bb[nf][1] = __float_as_uint(to_tf32(kp[4]));
                }
                mma_tf32(s[0], a, bb[0]);
                mma_tf32(s[1], a, bb[1]);
            }
            #pragma unroll
            for (int nf = 0; nf < 2; nf++)
                #pragma unroll
                for (int e = 0; e < 4; e++) {
                    int row = m0 + lq + ((e >= 2) ? 8 : 0);
                    int col = n0 + nf * 8 + lr * 2 + (e & 1);
                    float v = (col < klim) ? sigmoid_f(s[nf][e]) : 0.f;
                    sS[row * SSTR2 + col] = to_tf32(v);
                }
        }
        __syncthreads();

        {
            const int n0 = warp * 32;
            #pragma unroll
            for (int ks = 0; ks < 4; ks++) {
                uint32_t a[4][4], bb[4][2];
                #pragma unroll
                for (int mf = 0; mf < 4; mf++) {
                    const float* sp = sS + (mf * 16 + lq) * SSTR2 + ks * 8 + lr;
                    a[mf][0] = __float_as_uint(sp[0]);
                    a[mf][1] = __float_as_uint(sp[8 * SSTR2]);
                    a[mf][2] = __float_as_uint(sp[4]);
                    a[mf][3] = __float_as_uint(sp[8 * SSTR2 + 4]);
                }
                #pragma unroll
                for (int nf = 0; nf < 4; nf++) {
                    const float* vp = regV[buf] + (ks * 8 + lr) * KV_STR + n0 + nf * 8 + lq;
                    bb[nf][0] = __float_as_uint(to_tf32(vp[0]));
                    bb[nf][1] = __float_as_uint(to_tf32(vp[4 * KV_STR]));
                }
                #pragma unroll
                for (int mf = 0; mf < 4; mf++)
                    #pragma unroll
                    for (int nf = 0; nf < 4; nf++)
                        mma_tf32(o[mf][nf], a[mf], bb[nf]);
            }
        }
        __syncthreads();
    }

    // ---- store O tf32-rounded (only consumer is the 1x output GEMM) ----
    const int n0 = warp * 32;
    float* Obase = O + (size_t)(qs0 + qbeg) * DD;
    #pragma unroll
    for (int mf = 0; mf < 4; mf++)
        #pragma unroll
        for (int e = 0; e < 4; e++) {
            int row = mf * 16 + lq + ((e >= 2) ? 8 : 0);
            if (row >= qcnt) continue;
            #pragma unroll
            for (int nf = 0; nf < 4; nf++) {
                int col = n0 + nf * 8 + lr * 2 + (e & 1);
                Obase[(size_t)row * DD + col] = to_tf32(o[mf][nf][e]);
            }
        }
}

// ---------------- final output: concat(A_flat, R_flat) ----------------
__global__ void copy_out_kernel(float* __restrict__ out, int nA, int nR) {
    size_t na4 = (size_t)nA * DD / 4;
    size_t tot = (size_t)(nA + nR) * DD / 4;
    const float4* a4 = (const float4*)gA;
    const float4* r4 = (const float4*)gR;
    for (size_t i = blockIdx.x * (size_t)blockDim.x + threadIdx.x; i < tot;
         i += (size_t)gridDim.x * blockDim.x) {
        ((float4*)out)[i] = (i < na4) ? a4[i] : r4[i - na4];
    }
}

// ---------------- host launch ----------------
extern "C" void kernel_launch(void* const* d_in, const int* in_sizes, int n_in,
                              void* d_out, int out_size) {
    const float* fatoms = (const float*)d_in[0];
    const float* fres   = (const float*)d_in[1];
    const int* lig = (const int*)d_in[12];
    const int* res = (const int*)d_in[13];

    int nA = in_sizes[0] / DD;
    int nR = in_sizes[1] / DD;

    float *pA, *pR, *pAt, *pRt, *pAq, *pAk, *pAv, *pRq, *pRk, *pRv, *pTA, *pTR;
    float *pWp, *pWp1, *pInvA, *pInvR;
    cudaGetSymbolAddress((void**)&pA,  gA);
    cudaGetSymbolAddress((void**)&pR,  gR);
    cudaGetSymbolAddress((void**)&pAt, gAt);
    cudaGetSymbolAddress((void**)&pRt, gRt);
    cudaGetSymbolAddress((void**)&pAq, gAq);
    cudaGetSymbolAddress((void**)&pAk, gAk);
    cudaGetSymbolAddress((void**)&pAv, gAv);
    cudaGetSymbolAddress((void**)&pRq, gRq);
    cudaGetSymbolAddress((void**)&pRk, gRk);
    cudaGetSymbolAddress((void**)&pRv, gRv);
    cudaGetSymbolAddress((void**)&pTA, gTA);
    cudaGetSymbolAddress((void**)&pTR, gTR);
    cudaGetSymbolAddress((void**)&pWp, gWp);
    cudaGetSymbolAddress((void**)&pWp1, gWp1);
    cudaGetSymbolAddress((void**)&pInvA, gInvA);
    cudaGetSymbolAddress((void**)&pInvR, gInvR);

    cudaFuncSetAttribute(gemm_fused_kernel<1,3>, cudaFuncAttributeMaxDynamicSharedMemorySize, GEMM_SMEM3);
    cudaFuncSetAttribute(gemm_fused_kernel<0,1>, cudaFuncAttributeMaxDynamicSharedMemorySize, GEMM_SMEM1);
    cudaFuncSetAttribute(gemm_fused_kernel<2,1>, cudaFuncAttributeMaxDynamicSharedMemorySize, GEMM_SMEM1);
    cudaFuncSetAttribute(attn_mma_kernel, cudaFuncAttributeMaxDynamicSharedMemorySize, ATT_SMEM);

    // weight slot order: 0=W_lig_t 1=WQl 2=WKl 3=WVl 4=WOl | 5=W_res_t 6=WQr 7=WKr 8=WVr 9=WOr
    WIn win;
    win.w[0] = (const float*)d_in[2];
    win.w[1] = (const float*)d_in[4];
    win.w[2] = (const float*)d_in[5];
    win.w[3] = (const float*)d_in[6];
    win.w[4] = (const float*)d_in[7];
    win.w[5] = (const float*)d_in[3];
    win.w[6] = (const float*)d_in[8];
    win.w[7] = (const float*)d_in[9];
    win.w[8] = (const float*)d_in[10];
    win.w[9] = (const float*)d_in[11];

    const int aTiles = (nA + 127) / 128;
    const int rTiles = (nR + 127) / 128;
    const int totTiles = aTiles + rTiles;
    const int WSLOT3 = DD * DD * 2;
    const int WSLOT1 = DD * DD;

    fill_inv_kernel<<<256, 256>>>(lig, res);
    presplit_w_kernel<<<(10 * DD * DD + 255) / 256, 256>>>(win, pWp, pWp1);

    // init transforms (3x): A0 = leaky(fatoms@W_lig_t), R0 = leaky(fres@W_res_t)
    GArgs gi = {};
    gi.X[0] = fatoms; gi.X[1] = fres;
    gi.Wp[0][0] = pWp + 0 * WSLOT3; gi.Wp[1][0] = pWp + 5 * WSLOT3;
    gi.C[0][0] = pA; gi.C[1][0] = pR;
    gi.Ct[0] = pAt; gi.Ct[1] = pRt;
    gi.M[0] = nA; gi.M[1] = nR; gi.aTiles = aTiles;

    // fused QKV projections (1x, pre-rounded X, ldmatrix)
    GArgs gq = {};
    gq.X[0] = pAt; gq.X[1] = pRt;
    for (int j = 0; j < 3; j++) {
        gq.Wp[0][j] = pWp1 + (1 + j) * WSLOT1;
        gq.Wp[1][j] = pWp1 + (6 + j) * WSLOT1;
    }
    gq.C[0][0] = pAq; gq.C[0][1] = pAk; gq.C[0][2] = pAv;
    gq.C[1][0] = pRq; gq.C[1][1] = pRk; gq.C[1][2] = pRv;
    gq.M[0] = nA; gq.M[1] = nR; gq.aTiles = aTiles;

    // output GEMMs (1x): A = leaky(TA@WOl)*invA + A ; R = leaky(TR@WOr)*invR + R
    GArgs go = {};
    go.X[0] = pTA; go.X[1] = pTR;          // already tf32-rounded by attention store
    go.Wp[0][0] = pWp1 + 4 * WSLOT1; go.Wp[1][0] = pWp1 + 9 * WSLOT1;
    go.C[0][0] = pA; go.C[1][0] = pR;
    go.Ct[0] = pAt; go.Ct[1] = pRt;
    go.scale[0] = pInvA; go.scale[1] = pInvR;
    go.base[0] = pA; go.base[1] = pR;
    go.M[0] = nA; go.M[1] = nR; go.aTiles = aTiles;

    gemm_fused_kernel<1,3><<<dim3(4, totTiles), 256, GEMM_SMEM3>>>(gi);

    for (int it = 0; it < 3; it++) {
        gemm_fused_kernel<0,1><<<dim3(12, totTiles), 256, GEMM_SMEM1>>>(gq);

        // atoms attend to residues: Q=Aq (<=64 rows/complex), K/V = Rk/Rv
        attn_mma_kernel<<<dim3(256, 1), 256, ATT_SMEM>>>(pAq, pRk, pRv, pTA, lig, res);
        // residues attend to atoms: Q=Rq (64-row chunks), K/V = Ak/Av
        attn_mma_kernel<<<dim3(256, 8), 256, ATT_SMEM>>>(pRq, pAk, pAv, pTR, res, lig);

        gemm_fused_kernel<2,1><<<dim3(4, totTiles), 256, GEMM_SMEM1>>>(go);
    }

    copy_out_kernel<<<1024, 256>>>((float*)d_out, nA, nR);
}

// round 10
// speedup vs baseline: 1.2103x; 1.0679x over previous
#include <cuda_runtime.h>
#include <cstdint>

#define DD 256
#define NA_MAX (64*256)
#define NR_MAX (512*256)

// ---------------- scratch state (device globals; no allocation) ----------------
__device__ __align__(16) float gA  [NA_MAX*DD];   // state raw fp32
__device__ __align__(16) float gR  [NR_MAX*DD];
__device__ __align__(16) float gAt [NA_MAX*DD];   // state tf32-rounded (GEMM X input)
__device__ __align__(16) float gRt [NR_MAX*DD];
__device__ __align__(16) float gAq[NA_MAX*DD];    // QKV outputs: stored tf32-rounded
__device__ __align__(16) float gAk[NA_MAX*DD];
__device__ __align__(16) float gAv[NA_MAX*DD];
__device__ __align__(16) float gRq[NR_MAX*DD];
__device__ __align__(16) float gRk[NR_MAX*DD];
__device__ __align__(16) float gRv[NR_MAX*DD];
__device__ __align__(16) float gTA[NA_MAX*DD];    // attn out, stored tf32-rounded
__device__ __align__(16) float gTR[NR_MAX*DD];
__device__ __align__(16) float gWp [10*DD*DD*2];  // weights: fragment-major hi/lo (3x path)
__device__ __align__(16) float gWp1[10*DD*DD];    // weights: fragment-major hi only (1x path)
__device__ float gInvA[NA_MAX];
__device__ float gInvR[NR_MAX];

__device__ __forceinline__ float leaky_f(float x) { return x >= 0.f ? x : 0.1f * x; }
__device__ __forceinline__ float sigmoid_f(float x) {
    return __fdividef(1.f, 1.f + __expf(-x));
}
__device__ __forceinline__ float to_tf32(float x) {
    uint32_t u;
    asm("cvt.rna.tf32.f32 %0, %1;" : "=r"(u) : "f"(x));
    return __uint_as_float(u);
}
__device__ __forceinline__ void split_tf32(float x, float& hi, float& lo) {
    uint32_t u;
    asm("cvt.rna.tf32.f32 %0, %1;" : "=r"(u) : "f"(x));
    hi = __uint_as_float(u);
    float r = x - hi;
    uint32_t v;
    asm("cvt.rna.tf32.f32 %0, %1;" : "=r"(v) : "f"(r));
    lo = __uint_as_float(v);
}
__device__ __forceinline__ void mma_tf32(float* d, const uint32_t* a, const uint32_t* b) {
    asm volatile(
        "mma.sync.aligned.m16n8k8.row.col.f32.tf32.tf32.f32 "
        "{%0,%1,%2,%3}, {%4,%5,%6,%7}, {%8,%9}, {%0,%1,%2,%3};\n"
        : "+f"(d[0]), "+f"(d[1]), "+f"(d[2]), "+f"(d[3])
        : "r"(a[0]), "r"(a[1]), "r"(a[2]), "r"(a[3]), "r"(b[0]), "r"(b[1]));
}
__device__ __forceinline__ void ldsm_x4(uint32_t* r, uint32_t a) {
    asm volatile("ldmatrix.sync.aligned.m8n8.x4.shared.b16 {%0,%1,%2,%3}, [%4];"
        : "=r"(r[0]), "=r"(r[1]), "=r"(r[2]), "=r"(r[3]) : "r"(a));
}
__device__ __forceinline__ uint32_t smem_u32(const void* p) {
    return (uint32_t)__cvta_generic_to_shared(p);
}
__device__ __forceinline__ void cp16(uint32_t s, const void* g) {
    asm volatile("cp.async.cg.shared.global [%0], [%1], 16;\n" :: "r"(s), "l"(g));
}
__device__ __forceinline__ void cp_commit() { asm volatile("cp.async.commit_group;\n"); }
template <int N> __device__ __forceinline__ void cp_wait() {
    asm volatile("cp.async.wait_group %0;\n" :: "n"(N));
}

// ---------------- per-row 1/count scales ----------------
__global__ void fill_inv_kernel(const int* __restrict__ lig, const int* __restrict__ res) {
    int b = blockIdx.x;
    int as = lig[2*b], ac = lig[2*b+1];
    int rs = res[2*b], rc = res[2*b+1];
    float ia = 1.f / (float)rc;
    float ir = 1.f / (float)ac;
    for (int i = threadIdx.x; i < ac; i += blockDim.x) gInvA[as + i] = ia;
    for (int i = threadIdx.x; i < rc; i += blockDim.x) gInvR[rs + i] = ir;
}

// ---------------- weight presplit + permute (fragment-major) ----------------
struct WIn { const float* w[10]; };
__global__ void presplit_w_kernel(WIn win, float* __restrict__ wp, float* __restrict__ wp1) {
    int i = blockIdx.x * 256 + threadIdx.x;
    if (i >= 10 * DD * DD) return;
    int s = i >> 16, rem = i & 65535;
    int k = rem >> 8, n = rem & 255;
    float h, l;
    split_tf32(win.w[s][rem], h, l);
    int coltile = n >> 6, nf8 = (n >> 3) & 7, lq = n & 7;
    int ktile = k >> 5, kk = (k >> 3) & 3, lr = k & 3, khalf = (k >> 2) & 1;
    int lane = lq * 4 + lr;
    int chunk = (s * 4 + coltile) * 8 + ktile;
    int fr = (kk * 8 + nf8) * 32 + lane;
    size_t b3 = (size_t)chunk * 4096 + (size_t)fr * 4;
    wp[b3 + khalf] = h;
    wp[b3 + 2 + khalf] = l;
    size_t b1 = (size_t)chunk * 2048 + (size_t)fr * 2;
    wp1[b1 + khalf] = h;
}

// ---------------- fused tf32 pipelined GEMM (PREC 1|3, 2-stage) ----------------
// MODE 0: C = tf32(XW) ; 1: C = leaky(XW) (+Ct rounded) ; 2: C = leaky(XW)*scale+base (+Ct)
struct GArgs {
    const float* X[2];
    const float* Wp[2][3];
    float*       C[2][3];
    float*       Ct[2];
    const float* scale[2];
    const float* base[2];
    int M[2];
    int aTiles;
};

#define GX_STR 36
#define GA_FLOATS (128*GX_STR)             // 4608

template <int BKT>
__device__ __forceinline__ void gemm_stage(const float* X, const float* Wb,
                                           float* sXb, float* sBb,
                                           int row0, int M, int t, int tid)
{
    const int k0 = t * 32;
    #pragma unroll
    for (int j = 0; j < 4; j++) {
        int idx = tid + 256 * j;
        int row = idx >> 3, ch = idx & 7;
        int grow = row0 + row; if (grow > M - 1) grow = M - 1;   // clamp: garbage rows never stored
        cp16(smem_u32(sXb + row * GX_STR + ch * 4), X + (size_t)grow * DD + k0 + ch * 4);
    }
    const float* src = Wb + (size_t)t * BKT;
    #pragma unroll
    for (int j = 0; j < BKT / 1024; j++)
        cp16(smem_u32(sBb + (tid + 256 * j) * 4), src + (size_t)(tid + 256 * j) * 4);
}

template <int MODE, int PREC>
__global__ void __launch_bounds__(256, (PREC == 1) ? 3 : 2) gemm_fused_kernel(GArgs g)
{
    constexpr int BKT = (PREC == 3) ? 4096 : 2048;
    constexpr int STAGE = GA_FLOATS + BKT;
    extern __shared__ float smf[];

    const int side = (blockIdx.y >= g.aTiles) ? 1 : 0;
    const int rt = side ? blockIdx.y - g.aTiles : blockIdx.y;
    const int w = blockIdx.x >> 2, coltile = blockIdx.x & 3;
    const int col0 = coltile * 64;
    const int M = g.M[side];
    const int row0 = rt * 128;

    const float* X = g.X[side];
    const float* Wb = g.Wp[side][w] + (size_t)coltile * (8 * BKT);
    float* C = g.C[side][w];

    const int tid = threadIdx.x, lane = tid & 31, warp = tid >> 5;
    const int wm = warp >> 1, wn = warp & 1;
    const int lq = lane >> 2, lr = lane & 3;

    float* sX[2] = { smf,             smf + STAGE };
    float* sB[2] = { smf + GA_FLOATS, smf + STAGE + GA_FLOATS };

    float acc[2][4][4] = {};

    const int grp = lane >> 3, rr8 = lane & 7;
    const int arow_off = (grp & 1) * 8 + rr8;
    const int acol0 = (grp >> 1) * 4;

    gemm_stage<BKT>(X, Wb, sX[0], sB[0], row0, M, 0, tid);
    cp_commit();

    for (int t = 0; t < 8; t++) {
        int buf = t & 1;
        if (t < 7) {
            gemm_stage<BKT>(X, Wb, sX[buf ^ 1], sB[buf ^ 1], row0, M, t + 1, tid);
            cp_commit();
            cp_wait<1>();
        } else {
            cp_wait<0>();
        }
        __syncthreads();

        #pragma unroll
        for (int kk = 0; kk < 4; kk++) {
            uint32_t ah[2][4], al[2][4];
            if (PREC == 1) {
                #pragma unroll
                for (int mf = 0; mf < 2; mf++) {
                    uint32_t addr = smem_u32(sX[buf] + (wm * 32 + mf * 16 + arow_off) * GX_STR
                                             + kk * 8 + acol0);
                    ldsm_x4(ah[mf], addr);
                }
            } else {
                #pragma unroll
                for (int mf = 0; mf < 2; mf++) {
                    const float* xb = sX[buf] + (wm * 32 + mf * 16 + lq) * GX_STR + kk * 8 + lr;
                    float raw[4];
                    raw[0] = xb[0]; raw[1] = xb[8 * GX_STR];
                    raw[2] = xb[4]; raw[3] = xb[8 * GX_STR + 4];
                    #pragma unroll
                    for (int e = 0; e < 4; e++) {
                        float h, l;
                        split_tf32(raw[e], h, l);
                        ah[mf][e] = __float_as_uint(h);
                        al[mf][e] = __float_as_uint(l);
                    }
                }
            }
            #pragma unroll
            for (int nf = 0; nf < 4; nf++) {
                if (PREC == 3) {
                    float4 bv = *(const float4*)(sB[buf] + (size_t)((kk * 8 + wn * 4 + nf) * 32 + lane) * 4);
                    const uint32_t* bq = (const uint32_t*)&bv;
                    uint32_t bh[2] = { bq[0], bq[1] };
                    uint32_t bl[2] = { bq[2], bq[3] };
                    #pragma unroll
                    for (int mf = 0; mf < 2; mf++) {
                        mma_tf32(acc[mf][nf], al[mf], bh);
                        mma_tf32(acc[mf][nf], ah[mf], bl);
                        mma_tf32(acc[mf][nf], ah[mf], bh);
                    }
                } else {
                    float2 bv = *(const float2*)(sB[buf] + (size_t)((kk * 8 + wn * 4 + nf) * 32 + lane) * 2);
                    uint32_t bh[2] = { __float_as_uint(bv.x), __float_as_uint(bv.y) };
                    #pragma unroll
                    for (int mf = 0; mf < 2; mf++)
                        mma_tf32(acc[mf][nf], ah[mf], bh);
                }
            }
        }
        __syncthreads();
    }

    // ---- epilogue ----
    float* Ct = (MODE != 0) ? g.Ct[side] : nullptr;
    #pragma unroll
    for (int mf = 0; mf < 2; mf++) {
        #pragma unroll
        for (int i = 0; i < 4; i++) {
            int r = row0 + wm * 32 + mf * 16 + lq + ((i >= 2) ? 8 : 0);
            if (r >= M) continue;
            float sc = (MODE == 2) ? g.scale[side][r] : 0.f;
            #pragma unroll
            for (int nf = 0; nf < 4; nf++) {
                int c = col0 + wn * 32 + nf * 8 + lr * 2 + (i & 1);
                float v = acc[mf][nf][i];
                if (MODE == 0) {
                    C[(size_t)r * DD + c] = to_tf32(v);   // consumer (attention) rounds anyway
                } else {
                    if (MODE == 1) v = leaky_f(v);
                    if (MODE == 2) v = leaky_f(v) * sc + g.base[side][(size_t)r * DD + c];
                    C[(size_t)r * DD + c] = v;
                    Ct[(size_t)r * DD + c] = to_tf32(v);
                }
            }
        }
    }
}

#define GEMM_SMEM3 (2*(GA_FLOATS + 4096)*4)   // 69632 B
#define GEMM_SMEM1 (2*(GA_FLOATS + 2048)*4)   // 53248 B

// ---------------- merged mma sigmoid attention (both directions, one launch) ----------------
// grid (256, 9): y==0 -> atoms attend to residues; y>=1 -> residues chunk (y-1) attend to atoms.
// Q/K/V pre-rounded tf32 by the QKV GEMM. K staged stride 260 (ldsm-friendly),
// V stride 264 (scalar-load friendly), sS stride 36 (ldsm-friendly).
#define K_STR 260
#define V_STR 264
#define S_STR 36
#define ATT_QP 0                               // 16384 floats
#define ATT_SS 16384                           // 64*36 = 2304
#define ATT_R0 (16384 + 64*S_STR)              // 18688
#define ATT_REG (32*K_STR + 32*V_STR)          // 16768 floats per buffer region
#define ATT_R1 (ATT_R0 + ATT_REG)
#define ATT_SMEM ((ATT_R1 + ATT_REG) * 4)      // 208896 B

struct AArgs {
    const float* Q[2];
    const float* K[2];
    const float* V[2];
    float*       O[2];
    const int*   scQ[2];
    const int*   scKV[2];
};

__device__ __forceinline__ void attn_stage_kv(const float* K, const float* V,
                                              float* regKb, float* regVb,
                                              size_t kv0, int t0, int kvc, int tid)
{
    #pragma unroll
    for (int i = 0; i < 8; i++) {
        int idx = tid + 256 * i;
        int row = idx >> 6, ch = idx & 63;
        int gr = t0 + row; if (gr > kvc - 1) gr = kvc - 1;   // clamp: masked later
        cp16(smem_u32(regKb + row * K_STR + ch * 4), K + (kv0 + gr) * DD + ch * 4);
        cp16(smem_u32(regVb + row * V_STR + ch * 4), V + (kv0 + gr) * DD + ch * 4);
    }
}

__global__ void attn_mma_kernel(AArgs aa)
{
    extern __shared__ float smf[];
    float* Qp = smf + ATT_QP;
    float* sS = smf + ATT_SS;
    float* regK[2]; float* regV[2];
    regK[0] = smf + ATT_R0; regV[0] = regK[0] + 32 * K_STR;
    regK[1] = smf + ATT_R1; regV[1] = regK[1] + 32 * K_STR;
    float* Qraw = regK[0];   // region 0 aliased for initial Q staging (64*K_STR <= ATT_REG)

    const int role = (blockIdx.y == 0) ? 0 : 1;
    const int chunk = (blockIdx.y == 0) ? 0 : (int)blockIdx.y - 1;
    const float* Q = aa.Q[role];
    const float* K = aa.K[role];
    const float* V = aa.V[role];
    float* O = aa.O[role];

    const int b = blockIdx.x;
    const int qs0 = aa.scQ[role][2*b], qc = aa.scQ[role][2*b+1];
    const int kv0i = aa.scKV[role][2*b], kvc = aa.scKV[role][2*b+1];
    const int qbeg = chunk * 64;
    if (qbeg >= qc) return;
    const int qcnt = (qc - qbeg < 64) ? (qc - qbeg) : 64;

    const int tid = threadIdx.x, lane = tid & 31, warp = tid >> 5;
    const int lq = lane >> 2, lr = lane & 3;
    const int grp = lane >> 3, rr8 = lane & 7;
    const int arow_off = (grp & 1) * 8 + rr8;
    const int acol0 = (grp >> 1) * 4;

    // ---- stage Q (pre-rounded) into region 0 ----
    #pragma unroll
    for (int i = 0; i < 16; i++) {
        int idx = tid + 256 * i;
        int row = idx >> 6, ch = idx & 63;
        int gr = qbeg + row; if (gr > qc - 1) gr = qc - 1;
        cp16(smem_u32(Qraw + row * K_STR + ch * 4), Q + (size_t)(qs0 + gr) * DD + ch * 4);
    }
    cp_commit();
    attn_stage_kv(K, V, regK[1], regV[1], (size_t)kv0i, 0, kvc, tid);
    cp_commit();

    cp_wait<1>();
    __syncthreads();

    // ---- permute Q into fragment-major Qp (pure copy, already tf32) ----
    {
        int mt = warp >> 1;
        #pragma unroll
        for (int i = 0; i < 16; i++) {
            int kk = (warp & 1) * 16 + i;
            const float* qb = Qraw + (mt * 16 + lq) * K_STR + kk * 8 + lr;
            float4 v;
            v.x = qb[0];
            v.y = qb[8 * K_STR];
            v.z = qb[4];
            v.w = qb[8 * K_STR + 4];
            *(float4*)(Qp + ((size_t)(mt * 32 + kk) * 32 + lane) * 4) = v;
        }
    }
    __syncthreads();

    float o[4][4][4] = {};
    const int nT = (kvc + 31) >> 5;

    for (int t = 0; t < nT; t++) {
        int buf = (t & 1) ^ 1;
        if (t + 1 < nT) {
            attn_stage_kv(K, V, regK[buf ^ 1], regV[buf ^ 1], (size_t)kv0i, (t + 1) * 32, kvc, tid);
            cp_commit();
            cp_wait<1>();
        } else {
            cp_wait<0>();
        }
        __syncthreads();

        int klim = kvc - t * 32; if (klim > 32) klim = 32;

        // ---- phase S: 64x32 scores, K=256 ----
        {
            const int wm = warp >> 1, wn = warp & 1;
            const int m0 = wm * 16, n0 = wn * 16;
            float s[2][4] = {};
            #pragma unroll 4
            for (int kk = 0; kk < 32; kk++) {
                float4 qv = *(const float4*)(Qp + ((size_t)(wm * 32 + kk) * 32 + lane) * 4);
                uint32_t a[4] = { __float_as_uint(qv.x), __float_as_uint(qv.y),
                                  __float_as_uint(qv.z), __float_as_uint(qv.w) };
                uint32_t kr[4];
                ldsm_x4(kr, smem_u32(regK[buf] + (n0 + arow_off) * K_STR + kk * 8 + acol0));
                uint32_t b0[2] = { kr[0], kr[2] };
                uint32_t b1[2] = { kr[1], kr[3] };
                mma_tf32(s[0], a, b0);
                mma_tf32(s[1], a, b1);
            }
            #pragma unroll
            for (int nf = 0; nf < 2; nf++)
                #pragma unroll
                for (int e = 0; e < 4; e++) {
                    int row = m0 + lq + ((e >= 2) ? 8 : 0);
                    int col = n0 + nf * 8 + lr * 2 + (e & 1);
                    float v = (col < klim) ? sigmoid_f(s[nf][e]) : 0.f;
                    sS[row * S_STR + col] = to_tf32(v);
                }
        }
        __syncthreads();

        // ---- phase PV: O += S @ V (each warp owns 32 feature cols) ----
        {
            const int n0v = warp * 32;
            #pragma unroll
            for (int ks = 0; ks < 4; ks++) {
                uint32_t a[4][4], bb[4][2];
                #pragma unroll
                for (int mf = 0; mf < 4; mf++)
                    ldsm_x4(a[mf], smem_u32(sS + (mf * 16 + arow_off) * S_STR + ks * 8 + acol0));
                #pragma unroll
                for (int nf = 0; nf < 4; nf++) {
                    const float* vp = regV[buf] + (ks * 8 + lr) * V_STR + n0v + nf * 8 + lq;
                    bb[nf][0] = __float_as_uint(vp[0]);
                    bb[nf][1] = __float_as_uint(vp[4 * V_STR]);
                }
                #pragma unroll
                for (int mf = 0; mf < 4; mf++)
                    #pragma unroll
                    for (int nf = 0; nf < 4; nf++)
                        mma_tf32(o[mf][nf], a[mf], bb[nf]);
            }
        }
        __syncthreads();
    }

    // ---- store O tf32-rounded (only consumer is the 1x output GEMM) ----
    const int n0v = warp * 32;
    float* Obase = O + (size_t)(qs0 + qbeg) * DD;
    #pragma unroll
    for (int mf = 0; mf < 4; mf++)
        #pragma unroll
        for (int e = 0; e < 4; e++) {
            int row = mf * 16 + lq + ((e >= 2) ? 8 : 0);
            if (row >= qcnt) continue;
            #pragma unroll
            for (int nf = 0; nf < 4; nf++) {
                int col = n0v + nf * 8 + lr * 2 + (e & 1);
                Obase[(size_t)row * DD + col] = to_tf32(o[mf][nf][e]);
            }
        }
}

// ---------------- final output: concat(A_flat, R_flat) ----------------
__global__ void copy_out_kernel(float* __restrict__ out, int nA, int nR) {
    size_t na4 = (size_t)nA * DD / 4;
    size_t tot = (size_t)(nA + nR) * DD / 4;
    const float4* a4 = (const float4*)gA;
    const float4* r4 = (const float4*)gR;
    for (size_t i = blockIdx.x * (size_t)blockDim.x + threadIdx.x; i < tot;
         i += (size_t)gridDim.x * blockDim.x) {
        ((float4*)out)[i] = (i < na4) ? a4[i] : r4[i - na4];
    }
}

// ---------------- host launch ----------------
extern "C" void kernel_launch(void* const* d_in, const int* in_sizes, int n_in,
                              void* d_out, int out_size) {
    const float* fatoms = (const float*)d_in[0];
    const float* fres   = (const float*)d_in[1];
    const int* lig = (const int*)d_in[12];
    const int* res = (const int*)d_in[13];

    int nA = in_sizes[0] / DD;
    int nR = in_sizes[1] / DD;

    float *pA, *pR, *pAt, *pRt, *pAq, *pAk, *pAv, *pRq, *pRk, *pRv, *pTA, *pTR;
    float *pWp, *pWp1, *pInvA, *pInvR;
    cudaGetSymbolAddress((void**)&pA,  gA);
    cudaGetSymbolAddress((void**)&pR,  gR);
    cudaGetSymbolAddress((void**)&pAt, gAt);
    cudaGetSymbolAddress((void**)&pRt, gRt);
    cudaGetSymbolAddress((void**)&pAq, gAq);
    cudaGetSymbolAddress((void**)&pAk, gAk);
    cudaGetSymbolAddress((void**)&pAv, gAv);
    cudaGetSymbolAddress((void**)&pRq, gRq);
    cudaGetSymbolAddress((void**)&pRk, gRk);
    cudaGetSymbolAddress((void**)&pRv, gRv);
    cudaGetSymbolAddress((void**)&pTA, gTA);
    cudaGetSymbolAddress((void**)&pTR, gTR);
    cudaGetSymbolAddress((void**)&pWp, gWp);
    cudaGetSymbolAddress((void**)&pWp1, gWp1);
    cudaGetSymbolAddress((void**)&pInvA, gInvA);
    cudaGetSymbolAddress((void**)&pInvR, gInvR);

    cudaFuncSetAttribute(gemm_fused_kernel<1,3>, cudaFuncAttributeMaxDynamicSharedMemorySize, GEMM_SMEM3);
    cudaFuncSetAttribute(gemm_fused_kernel<0,1>, cudaFuncAttributeMaxDynamicSharedMemorySize, GEMM_SMEM1);
    cudaFuncSetAttribute(gemm_fused_kernel<2,1>, cudaFuncAttributeMaxDynamicSharedMemorySize, GEMM_SMEM1);
    cudaFuncSetAttribute(attn_mma_kernel, cudaFuncAttributeMaxDynamicSharedMemorySize, ATT_SMEM);

    // weight slot order: 0=W_lig_t 1=WQl 2=WKl 3=WVl 4=WOl | 5=W_res_t 6=WQr 7=WKr 8=WVr 9=WOr
    WIn win;
    win.w[0] = (const float*)d_in[2];
    win.w[1] = (const float*)d_in[4];
    win.w[2] = (const float*)d_in[5];
    win.w[3] = (const float*)d_in[6];
    win.w[4] = (const float*)d_in[7];
    win.w[5] = (const float*)d_in[3];
    win.w[6] = (const float*)d_in[8];
    win.w[7] = (const float*)d_in[9];
    win.w[8] = (const float*)d_in[10];
    win.w[9] = (const float*)d_in[11];

    const int aTiles = (nA + 127) / 128;
    const int rTiles = (nR + 127) / 128;
    const int totTiles = aTiles + rTiles;
    const int WSLOT3 = DD * DD * 2;
    const int WSLOT1 = DD * DD;

    fill_inv_kernel<<<256, 256>>>(lig, res);
    presplit_w_kernel<<<(10 * DD * DD + 255) / 256, 256>>>(win, pWp, pWp1);

    // init transforms (3x): A0 = leaky(fatoms@W_lig_t), R0 = leaky(fres@W_res_t)
    GArgs gi = {};
    gi.X[0] = fatoms; gi.X[1] = fres;
    gi.Wp[0][0] = pWp + 0 * WSLOT3; gi.Wp[1][0] = pWp + 5 * WSLOT3;
    gi.C[0][0] = pA; gi.C[1][0] = pR;
    gi.Ct[0] = pAt; gi.Ct[1] = pRt;
    gi.M[0] = nA; gi.M[1] = nR; gi.aTiles = aTiles;

    // fused QKV projections (1x, pre-rounded X, rounded outputs)
    GArgs gq = {};
    gq.X[0] = pAt; gq.X[1] = pRt;
    for (int j = 0; j < 3; j++) {
        gq.Wp[0][j] = pWp1 + (1 + j) * WSLOT1;
        gq.Wp[1][j] = pWp1 + (6 + j) * WSLOT1;
    }
    gq.C[0][0] = pAq; gq.C[0][1] = pAk; gq.C[0][2] = pAv;
    gq.C[1][0] = pRq; gq.C[1][1] = pRk; gq.C[1][2] = pRv;
    gq.M[0] = nA; gq.M[1] = nR; gq.aTiles = aTiles;

    // output GEMMs (1x): A = leaky(TA@WOl)*invA + A ; R = leaky(TR@WOr)*invR + R
    GArgs go = {};
    go.X[0] = pTA; go.X[1] = pTR;          // already tf32-rounded by attention store
    go.Wp[0][0] = pWp1 + 4 * WSLOT1; go.Wp[1][0] = pWp1 + 9 * WSLOT1;
    go.C[0][0] = pA; go.C[1][0] = pR;
    go.Ct[0] = pAt; go.Ct[1] = pRt;
    go.scale[0] = pInvA; go.scale[1] = pInvR;
    go.base[0] = pA; go.base[1] = pR;
    go.M[0] = nA; go.M[1] = nR; go.aTiles = aTiles;

    // merged attention: role 0 = atoms->residues, role 1 = residues->atoms
    AArgs aa = {};
    aa.Q[0] = pAq; aa.K[0] = pRk; aa.V[0] = pRv; aa.O[0] = pTA;
    aa.scQ[0] = lig; aa.scKV[0] = res;
    aa.Q[1] = pRq; aa.K[1] = pAk; aa.V[1] = pAv; aa.O[1] = pTR;
    aa.scQ[1] = res; aa.scKV[1] = lig;

    gemm_fused_kernel<1,3><<<dim3(4, totTiles), 256, GEMM_SMEM3>>>(gi);

    for (int it = 0; it < 3; it++) {
        gemm_fused_kernel<0,1><<<dim3(12, totTiles), 256, GEMM_SMEM1>>>(gq);

        attn_mma_kernel<<<dim3(256, 9), 256, ATT_SMEM>>>(aa);

        gemm_fused_kernel<2,1><<<dim3(4, totTiles), 256, GEMM_SMEM1>>>(go);
    }

    copy_out_kernel<<<1024, 256>>>((float*)d_out, nA, nR);
}

// round 11
// speedup vs baseline: 1.2885x; 1.0646x over previous
#include <cuda_runtime.h>
#include <cstdint>

#define DD 256
#define NA_MAX (64*256)
#define NR_MAX (512*256)

// ---------------- scratch state (device globals; no allocation) ----------------
__device__ __align__(16) float gA  [NA_MAX*DD];   // state raw fp32
__device__ __align__(16) float gR  [NR_MAX*DD];
__device__ __align__(16) float gAt [NA_MAX*DD];   // state tf32-rounded (GEMM X input)
__device__ __align__(16) float gRt [NR_MAX*DD];
__device__ __align__(16) float gAq[NA_MAX*DD];    // QKV outputs: stored tf32-rounded
__device__ __align__(16) float gAk[NA_MAX*DD];
__device__ __align__(16) float gAv[NA_MAX*DD];
__device__ __align__(16) float gRq[NR_MAX*DD];
__device__ __align__(16) float gRk[NR_MAX*DD];
__device__ __align__(16) float gRv[NR_MAX*DD];
__device__ __align__(16) float gTA[NA_MAX*DD];    // attn out, stored tf32-rounded
__device__ __align__(16) float gTR[NR_MAX*DD];
__device__ __align__(16) float gWp [10*DD*DD*2];  // weights: fragment-major hi/lo (3x path)
__device__ __align__(16) float gWp1[10*DD*DD];    // weights: fragment-major hi only (1x path)
__device__ float gInvA[NA_MAX];
__device__ float gInvR[NR_MAX];

__device__ __forceinline__ float leaky_f(float x) { return x >= 0.f ? x : 0.1f * x; }
__device__ __forceinline__ float sigmoid_f(float x) {
    return __fdividef(1.f, 1.f + __expf(-x));
}
__device__ __forceinline__ float to_tf32(float x) {
    uint32_t u;
    asm("cvt.rna.tf32.f32 %0, %1;" : "=r"(u) : "f"(x));
    return __uint_as_float(u);
}
__device__ __forceinline__ void split_tf32(float x, float& hi, float& lo) {
    uint32_t u;
    asm("cvt.rna.tf32.f32 %0, %1;" : "=r"(u) : "f"(x));
    hi = __uint_as_float(u);
    float r = x - hi;
    uint32_t v;
    asm("cvt.rna.tf32.f32 %0, %1;" : "=r"(v) : "f"(r));
    lo = __uint_as_float(v);
}
__device__ __forceinline__ void mma_tf32(float* d, const uint32_t* a, const uint32_t* b) {
    asm volatile(
        "mma.sync.aligned.m16n8k8.row.col.f32.tf32.tf32.f32 "
        "{%0,%1,%2,%3}, {%4,%5,%6,%7}, {%8,%9}, {%0,%1,%2,%3};\n"
        : "+f"(d[0]), "+f"(d[1]), "+f"(d[2]), "+f"(d[3])
        : "r"(a[0]), "r"(a[1]), "r"(a[2]), "r"(a[3]), "r"(b[0]), "r"(b[1]));
}
__device__ __forceinline__ void ldsm_x4(uint32_t* r, uint32_t a) {
    asm volatile("ldmatrix.sync.aligned.m8n8.x4.shared.b16 {%0,%1,%2,%3}, [%4];"
        : "=r"(r[0]), "=r"(r[1]), "=r"(r[2]), "=r"(r[3]) : "r"(a));
}
__device__ __forceinline__ uint32_t smem_u32(const void* p) {
    return (uint32_t)__cvta_generic_to_shared(p);
}
__device__ __forceinline__ void cp16(uint32_t s, const void* g) {
    asm volatile("cp.async.cg.shared.global [%0], [%1], 16;\n" :: "r"(s), "l"(g));
}
__device__ __forceinline__ void cp_commit() { asm volatile("cp.async.commit_group;\n"); }
template <int N> __device__ __forceinline__ void cp_wait() {
    asm volatile("cp.async.wait_group %0;\n" :: "n"(N));
}

// ---------------- per-row 1/count scales ----------------
__global__ void fill_inv_kernel(const int* __restrict__ lig, const int* __restrict__ res) {
    int b = blockIdx.x;
    int as = lig[2*b], ac = lig[2*b+1];
    int rs = res[2*b], rc = res[2*b+1];
    float ia = 1.f / (float)rc;
    float ir = 1.f / (float)ac;
    for (int i = threadIdx.x; i < ac; i += blockDim.x) gInvA[as + i] = ia;
    for (int i = threadIdx.x; i < rc; i += blockDim.x) gInvR[rs + i] = ir;
}

// ---------------- weight presplit + permute (fragment-major) ----------------
struct WIn { const float* w[10]; };
__global__ void presplit_w_kernel(WIn win, float* __restrict__ wp, float* __restrict__ wp1) {
    int i = blockIdx.x * 256 + threadIdx.x;
    if (i >= 10 * DD * DD) return;
    int s = i >> 16, rem = i & 65535;
    int k = rem >> 8, n = rem & 255;
    float h, l;
    split_tf32(win.w[s][rem], h, l);
    int coltile = n >> 6, nf8 = (n >> 3) & 7, lq = n & 7;
    int ktile = k >> 5, kk = (k >> 3) & 3, lr = k & 3, khalf = (k >> 2) & 1;
    int lane = lq * 4 + lr;
    int chunk = (s * 4 + coltile) * 8 + ktile;
    int fr = (kk * 8 + nf8) * 32 + lane;
    size_t b3 = (size_t)chunk * 4096 + (size_t)fr * 4;
    wp[b3 + khalf] = h;
    wp[b3 + 2 + khalf] = l;
    size_t b1 = (size_t)chunk * 2048 + (size_t)fr * 2;
    wp1[b1 + khalf] = h;
}

// ---------------- fused tf32 pipelined GEMM (PREC 1|3, NT coltiles, 2-stage) ----------------
// MODE 0: C = tf32(XW) ; 1: C = leaky(XW) (+Ct rounded) ; 2: C = leaky(XW)*scale+base (+Ct)
struct GArgs {
    const float* X[2];
    const float* Wp[2][3];
    float*       C[2][3];
    float*       Ct[2];
    const float* scale[2];
    const float* base[2];
    int M[2];
    int aTiles;
};

#define GX_STR 36
#define GA_FLOATS (128*GX_STR)             // 4608

template <int BKT1, int NT>
__device__ __forceinline__ void gemm_stage(const float* X, const float* Wb,
                                           float* sXb, float* sBb,
                                           int row0, int M, int t, int tid)
{
    const int k0 = t * 32;
    #pragma unroll
    for (int j = 0; j < 4; j++) {
        int idx = tid + 256 * j;
        int row = idx >> 3, ch = idx & 7;
        int grow = row0 + row; if (grow > M - 1) grow = M - 1;   // clamp: garbage rows never stored
        cp16(smem_u32(sXb + row * GX_STR + ch * 4), X + (size_t)grow * DD + k0 + ch * 4);
    }
    #pragma unroll
    for (int ct = 0; ct < NT; ct++) {
        const float* src = Wb + (size_t)(ct * 8 + t) * BKT1;
        #pragma unroll
        for (int j = 0; j < BKT1 / 1024; j++)
            cp16(smem_u32(sBb + ct * BKT1 + (tid + 256 * j) * 4), src + (size_t)(tid + 256 * j) * 4);
    }
}

template <int MODE, int PREC, int NT>
__global__ void __launch_bounds__(256, (PREC == 1 && NT == 1) ? 3 : 2) gemm_fused_kernel(GArgs g)
{
    constexpr int BKT1 = (PREC == 3) ? 4096 : 2048;
    constexpr int BKT = NT * BKT1;
    constexpr int STAGE = GA_FLOATS + BKT;
    constexpr int NF = 4 * NT;
    constexpr int CGRP = 4 / NT;
    extern __shared__ float smf[];

    const int side = (blockIdx.y >= g.aTiles) ? 1 : 0;
    const int rt = side ? blockIdx.y - g.aTiles : blockIdx.y;
    const int w = blockIdx.x / CGRP;
    const int cg = blockIdx.x % CGRP;
    const int col0 = cg * (64 * NT);
    const int M = g.M[side];
    const int row0 = rt * 128;

    const float* X = g.X[side];
    const float* Wb = g.Wp[side][w] + (size_t)(cg * NT) * (8 * BKT1);
    float* C = g.C[side][w];

    const int tid = threadIdx.x, lane = tid & 31, warp = tid >> 5;
    const int wm = warp >> 1, wn = warp & 1;
    const int lq = lane >> 2, lr = lane & 3;

    float* sX[2] = { smf,             smf + STAGE };
    float* sB[2] = { smf + GA_FLOATS, smf + STAGE + GA_FLOATS };

    float acc[2][NF][4] = {};

    const int grp = lane >> 3, rr8 = lane & 7;
    const int arow_off = (grp & 1) * 8 + rr8;
    const int acol0 = (grp >> 1) * 4;

    gemm_stage<BKT1, NT>(X, Wb, sX[0], sB[0], row0, M, 0, tid);
    cp_commit();

    for (int t = 0; t < 8; t++) {
        int buf = t & 1;
        if (t < 7) {
            gemm_stage<BKT1, NT>(X, Wb, sX[buf ^ 1], sB[buf ^ 1], row0, M, t + 1, tid);
            cp_commit();
            cp_wait<1>();
        } else {
            cp_wait<0>();
        }
        __syncthreads();

        #pragma unroll
        for (int kk = 0; kk < 4; kk++) {
            uint32_t ah[2][4], al[2][4];
            if (PREC == 1) {
                #pragma unroll
                for (int mf = 0; mf < 2; mf++) {
                    uint32_t addr = smem_u32(sX[buf] + (wm * 32 + mf * 16 + arow_off) * GX_STR
                                             + kk * 8 + acol0);
                    ldsm_x4(ah[mf], addr);
                }
            } else {
                #pragma unroll
                for (int mf = 0; mf < 2; mf++) {
                    const float* xb = sX[buf] + (wm * 32 + mf * 16 + lq) * GX_STR + kk * 8 + lr;
                    float raw[4];
                    raw[0] = xb[0]; raw[1] = xb[8 * GX_STR];
                    raw[2] = xb[4]; raw[3] = xb[8 * GX_STR + 4];
                    #pragma unroll
                    for (int e = 0; e < 4; e++) {
                        float h, l;
                        split_tf32(raw[e], h, l);
                        ah[mf][e] = __float_as_uint(h);
                        al[mf][e] = __float_as_uint(l);
                    }
                }
            }
            #pragma unroll
            for (int nf = 0; nf < NF; nf++) {
                const int ct = nf >> 2, nfi = nf & 3;
                if (PREC == 3) {
                    float4 bv = *(const float4*)(sB[buf] + ct * BKT1
                                 + (size_t)((kk * 8 + wn * 4 + nfi) * 32 + lane) * 4);
                    const uint32_t* bq = (const uint32_t*)&bv;
                    uint32_t bh[2] = { bq[0], bq[1] };
                    uint32_t bl[2] = { bq[2], bq[3] };
                    #pragma unroll
                    for (int mf = 0; mf < 2; mf++) {
                        mma_tf32(acc[mf][nf], al[mf], bh);
                        mma_tf32(acc[mf][nf], ah[mf], bl);
                        mma_tf32(acc[mf][nf], ah[mf], bh);
                    }
                } else {
                    float2 bv = *(const float2*)(sB[buf] + ct * BKT1
                                 + (size_t)((kk * 8 + wn * 4 + nfi) * 32 + lane) * 2);
                    uint32_t bh[2] = { __float_as_uint(bv.x), __float_as_uint(bv.y) };
                    #pragma unroll
                    for (int mf = 0; mf < 2; mf++)
                        mma_tf32(acc[mf][nf], ah[mf], bh);
                }
            }
        }
        __syncthreads();
    }

    // ---- epilogue ----
    float* Ct = (MODE != 0) ? g.Ct[side] : nullptr;
    #pragma unroll
    for (int mf = 0; mf < 2; mf++) {
        #pragma unroll
        for (int i = 0; i < 4; i++) {
            int r = row0 + wm * 32 + mf * 16 + lq + ((i >= 2) ? 8 : 0);
            if (r >= M) continue;
            float sc = (MODE == 2) ? g.scale[side][r] : 0.f;
            #pragma unroll
            for (int nf = 0; nf < NF; nf++) {
                int c = col0 + (nf >> 2) * 64 + wn * 32 + (nf & 3) * 8 + lr * 2 + (i & 1);
                float v = acc[mf][nf][i];
                if (MODE == 0) {
                    C[(size_t)r * DD + c] = to_tf32(v);   // consumer (attention) rounds anyway
                } else {
                    if (MODE == 1) v = leaky_f(v);
                    if (MODE == 2) v = leaky_f(v) * sc + g.base[side][(size_t)r * DD + c];
                    C[(size_t)r * DD + c] = v;
                    Ct[(size_t)r * DD + c] = to_tf32(v);
                }
            }
        }
    }
}

#define GEMM_SMEM0 (2*(GA_FLOATS + 2*2048)*4)  // 69632 B  (MODE0, PREC1, NT2)
#define GEMM_SMEM3 (2*(GA_FLOATS + 4096)*4)    // 69632 B  (init, PREC3, NT1)
#define GEMM_SMEM1 (2*(GA_FLOATS + 2048)*4)    // 53248 B  (out, PREC1, NT1)

// ---------------- merged mma sigmoid attention (64-row KV tiles, alternating K/V buffers) ----------------
// grid (256, 9): y==0 -> atoms attend to residues; y>=1 -> residues chunk (y-1) attend to atoms.
// Q/K/V pre-rounded tf32. Strides: Q/K 260, V 264, sS 68 (all ldsm/scalar conflict-free).
#define K_STR 260
#define V_STR 264
#define S_STR 68
#define ATT_K (64*K_STR)                    // 16640 (Q region size)
#define ATT_V (ATT_K + 64*K_STR)            // 33280
#define ATT_S (ATT_V + 64*V_STR)            // 50176
#define ATT_SMEM ((ATT_S + 64*S_STR)*4)     // 218112 B

struct AArgs {
    const float* Q[2];
    const float* K[2];
    const float* V[2];
    float*       O[2];
    const int*   scQ[2];
    const int*   scKV[2];
};

__device__ __forceinline__ void attn_stage64(const float* G, float* sdst, int str,
                                             size_t base0, int r0, int rmax, int tid)
{
    #pragma unroll
    for (int i = 0; i < 16; i++) {
        int idx = tid + 256 * i;
        int row = idx >> 6, ch = idx & 63;
        int gr = r0 + row; if (gr > rmax) gr = rmax;   // clamp: masked/never-stored later
        cp16(smem_u32(sdst + row * str + ch * 4), G + (base0 + gr) * DD + ch * 4);
    }
}

__global__ void attn_mma_kernel(AArgs aa)
{
    extern __shared__ float smf[];
    float* sQ = smf;
    float* sK = smf + ATT_K;
    float* sV = smf + ATT_V;
    float* sS = smf + ATT_S;

    const int role = (blockIdx.y == 0) ? 0 : 1;
    const int chunk = (blockIdx.y == 0) ? 0 : (int)blockIdx.y - 1;
    const float* Q = aa.Q[role];
    const float* K = aa.K[role];
    const float* V = aa.V[role];
    float* O = aa.O[role];

    const int b = blockIdx.x;
    const int qs0 = aa.scQ[role][2*b], qc = aa.scQ[role][2*b+1];
    const int kv0i = aa.scKV[role][2*b], kvc = aa.scKV[role][2*b+1];
    const int qbeg = chunk * 64;
    if (qbeg >= qc) return;
    const int qcnt = (qc - qbeg < 64) ? (qc - qbeg) : 64;

    const int tid = threadIdx.x, lane = tid & 31, warp = tid >> 5;
    const int lq = lane >> 2, lr = lane & 3;
    const int grp = lane >> 3, rr8 = lane & 7;
    const int arow_off = (grp & 1) * 8 + rr8;
    const int acol0 = (grp >> 1) * 4;

    // prologue: stage Q + K0 (group), then V0 (group)
    attn_stage64(Q, sQ, K_STR, (size_t)qs0, qbeg, qc - 1, tid);
    attn_stage64(K, sK, K_STR, (size_t)kv0i, 0, kvc - 1, tid);
    cp_commit();
    attn_stage64(V, sV, V_STR, (size_t)kv0i, 0, kvc - 1, tid);
    cp_commit();

    float o[4][4][4] = {};
    const int nT = (kvc + 63) >> 6;

    for (int t = 0; t < nT; t++) {
        cp_wait<1>();            // K[t] (and Q at t=0) complete; V[t] may be in flight
        __syncthreads();
        int klim = kvc - t * 64; if (klim > 64) klim = 64;

        // ---- phase S: 64x64 scores, K=256; 8 warps as 2(m) x 4(n), warp tile 32x16 ----
        {
            const int wmS = warp >> 2, wnS = warp & 3;
            const int m0 = wmS * 32, n0 = wnS * 16;
            float s[2][2][4] = {};
            #pragma unroll 4
            for (int kk = 0; kk < 32; kk++) {
                uint32_t a[2][4];
                ldsm_x4(a[0], smem_u32(sQ + (m0 + arow_off) * K_STR + kk * 8 + acol0));
                ldsm_x4(a[1], smem_u32(sQ + (m0 + 16 + arow_off) * K_STR + kk * 8 + acol0));
                uint32_t kr[4];
                ldsm_x4(kr, smem_u32(sK + (n0 + arow_off) * K_STR + kk * 8 + acol0));
                uint32_t b0[2] = { kr[0], kr[2] };
                uint32_t b1[2] = { kr[1], kr[3] };
                mma_tf32(s[0][0], a[0], b0); mma_tf32(s[0][1], a[0], b1);
                mma_tf32(s[1][0], a[1], b0); mma_tf32(s[1][1], a[1], b1);
            }
            #pragma unroll
            for (int mf = 0; mf < 2; mf++)
                #pragma unroll
                for (int nf = 0; nf < 2; nf++)
                    #pragma unroll
                    for (int e = 0; e < 4; e++) {
                        int row = m0 + mf * 16 + lq + ((e >= 2) ? 8 : 0);
                        int col = n0 + nf * 8 + lr * 2 + (e & 1);
                        float v = (col < klim) ? sigmoid_f(s[mf][nf][e]) : 0.f;
                        sS[row * S_STR + col] = to_tf32(v);
                    }
        }
        __syncthreads();         // sS ready; sK free
        if (t + 1 < nT)
            attn_stage64(K, sK, K_STR, (size_t)kv0i, (t + 1) * 64, kvc - 1, tid);
        cp_commit();             // group K[t+1] (possibly empty)
        cp_wait<1>();            // V[t] complete (pending: K[t+1])
        __syncthreads();

        // ---- phase PV: O += S @ V; each warp owns 32 feature cols; ks 0..7 ----
        {
            const int n0v = warp * 32;
            #pragma unroll
            for (int ks = 0; ks < 8; ks++) {
                uint32_t a[4][4], bb[4][2];
                #pragma unroll
                for (int mf = 0; mf < 4; mf++)
                    ldsm_x4(a[mf], smem_u32(sS + (mf * 16 + arow_off) * S_STR + ks * 8 + acol0));
                #pragma unroll
                for (int nf = 0; nf < 4; nf++) {
                    const float* vp = sV + (ks * 8 + lr) * V_STR + n0v + nf * 8 + lq;
                    bb[nf][0] = __float_as_uint(vp[0]);
                    bb[nf][1] = __float_as_uint(vp[4 * V_STR]);
                }
                #pragma unroll
                for (int mf = 0; mf < 4; mf++)
                    #pragma unroll
                    for (int nf = 0; nf < 4; nf++)
                        mma_tf32(o[mf][nf], a[mf], bb[nf]);
            }
        }
        __syncthreads();         // sV, sS free
        if (t + 1 < nT)
            attn_stage64(V, sV, V_STR, (size_t)kv0i, (t + 1) * 64, kvc - 1, tid);
        cp_commit();             // group V[t+1] (possibly empty)
    }

    // ---- store O tf32-rounded (only consumer is the 1x output GEMM) ----
    const int n0v = warp * 32;
    float* Obase = O + (size_t)(qs0 + qbeg) * DD;
    #pragma unroll
    for (int mf = 0; mf < 4; mf++)
        #pragma unroll
        for (int e = 0; e < 4; e++) {
            int row = mf * 16 + lq + ((e >= 2) ? 8 : 0);
            if (row >= qcnt) continue;
            #pragma unroll
            for (int nf = 0; nf < 4; nf++) {
                int col = n0v + nf * 8 + lr * 2 + (e & 1);
                Obase[(size_t)row * DD + col] = to_tf32(o[mf][nf][e]);
            }
        }
}

// ---------------- final output: concat(A_flat, R_flat) ----------------
__global__ void copy_out_kernel(float* __restrict__ out, int nA, int nR) {
    size_t na4 = (size_t)nA * DD / 4;
    size_t tot = (size_t)(nA + nR) * DD / 4;
    const float4* a4 = (const float4*)gA;
    const float4* r4 = (const float4*)gR;
    for (size_t i = blockIdx.x * (size_t)blockDim.x + threadIdx.x; i < tot;
         i += (size_t)gridDim.x * blockDim.x) {
        ((float4*)out)[i] = (i < na4) ? a4[i] : r4[i - na4];
    }
}

// ---------------- host launch ----------------
extern "C" void kernel_launch(void* const* d_in, const int* in_sizes, int n_in,
                              void* d_out, int out_size) {
    const float* fatoms = (const float*)d_in[0];
    const float* fres   = (const float*)d_in[1];
    const int* lig = (const int*)d_in[12];
    const int* res = (const int*)d_in[13];

    int nA = in_sizes[0] / DD;
    int nR = in_sizes[1] / DD;

    float *pA, *pR, *pAt, *pRt, *pAq, *pAk, *pAv, *pRq, *pRk, *pRv, *pTA, *pTR;
    float *pWp, *pWp1, *pInvA, *pInvR;
    cudaGetSymbolAddress((void**)&pA,  gA);
    cudaGetSymbolAddress((void**)&pR,  gR);
    cudaGetSymbolAddress((void**)&pAt, gAt);
    cudaGetSymbolAddress((void**)&pRt, gRt);
    cudaGetSymbolAddress((void**)&pAq, gAq);
    cudaGetSymbolAddress((void**)&pAk, gAk);
    cudaGetSymbolAddress((void**)&pAv, gAv);
    cudaGetSymbolAddress((void**)&pRq, gRq);
    cudaGetSymbolAddress((void**)&pRk, gRk);
    cudaGetSymbolAddress((void**)&pRv, gRv);
    cudaGetSymbolAddress((void**)&pTA, gTA);
    cudaGetSymbolAddress((void**)&pTR, gTR);
    cudaGetSymbolAddress((void**)&pWp, gWp);
    cudaGetSymbolAddress((void**)&pWp1, gWp1);
    cudaGetSymbolAddress((void**)&pInvA, gInvA);
    cudaGetSymbolAddress((void**)&pInvR, gInvR);

    cudaFuncSetAttribute(gemm_fused_kernel<1,3,1>, cudaFuncAttributeMaxDynamicSharedMemorySize, GEMM_SMEM3);
    cudaFuncSetAttribute(gemm_fused_kernel<0,1,2>, cudaFuncAttributeMaxDynamicSharedMemorySize, GEMM_SMEM0);
    cudaFuncSetAttribute(gemm_fused_kernel<2,1,1>, cudaFuncAttributeMaxDynamicSharedMemorySize, GEMM_SMEM1);
    cudaFuncSetAttribute(attn_mma_kernel, cudaFuncAttributeMaxDynamicSharedMemorySize, ATT_SMEM);

    // weight slot order: 0=W_lig_t 1=WQl 2=WKl 3=WVl 4=WOl | 5=W_res_t 6=WQr 7=WKr 8=WVr 9=WOr
    WIn win;
    win.w[0] = (const float*)d_in[2];
    win.w[1] = (const float*)d_in[4];
    win.w[2] = (const float*)d_in[5];
    win.w[3] = (const float*)d_in[6];
    win.w[4] = (const float*)d_in[7];
    win.w[5] = (const float*)d_in[3];
    win.w[6] = (const float*)d_in[8];
    win.w[7] = (const float*)d_in[9];
    win.w[8] = (const float*)d_in[10];
    win.w[9] = (const float*)d_in[11];

    const int aTiles = (nA + 127) / 128;
    const int rTiles = (nR + 127) / 128;
    const int totTiles = aTiles + rTiles;
    const int WSLOT3 = DD * DD * 2;
    const int WSLOT1 = DD * DD;

    fill_inv_kernel<<<256, 256>>>(lig, res);
    presplit_w_kernel<<<(10 * DD * DD + 255) / 256, 256>>>(win, pWp, pWp1);

    // init transforms (3x): A0 = leaky(fatoms@W_lig_t), R0 = leaky(fres@W_res_t)
    GArgs gi = {};
    gi.X[0] = fatoms; gi.X[1] = fres;
    gi.Wp[0][0] = pWp + 0 * WSLOT3; gi.Wp[1][0] = pWp + 5 * WSLOT3;
    gi.C[0][0] = pA; gi.C[1][0] = pR;
    gi.Ct[0] = pAt; gi.Ct[1] = pRt;
    gi.M[0] = nA; gi.M[1] = nR; gi.aTiles = aTiles;

    // fused QKV projections (1x, NT=2, pre-rounded X, rounded outputs)
    GArgs gq = {};
    gq.X[0] = pAt; gq.X[1] = pRt;
    for (int j = 0; j < 3; j++) {
        gq.Wp[0][j] = pWp1 + (1 + j) * WSLOT1;
        gq.Wp[1][j] = pWp1 + (6 + j) * WSLOT1;
    }
    gq.C[0][0] = pAq; gq.C[0][1] = pAk; gq.C[0][2] = pAv;
    gq.C[1][0] = pRq; gq.C[1][1] = pRk; gq.C[1][2] = pRv;
    gq.M[0] = nA; gq.M[1] = nR; gq.aTiles = aTiles;

    // output GEMMs (1x): A = leaky(TA@WOl)*invA + A ; R = leaky(TR@WOr)*invR + R
    GArgs go = {};
    go.X[0] = pTA; go.X[1] = pTR;          // already tf32-rounded by attention store
    go.Wp[0][0] = pWp1 + 4 * WSLOT1; go.Wp[1][0] = pWp1 + 9 * WSLOT1;
    go.C[0][0] = pA; go.C[1][0] = pR;
    go.Ct[0] = pAt; go.Ct[1] = pRt;
    go.scale[0] = pInvA; go.scale[1] = pInvR;
    go.base[0] = pA; go.base[1] = pR;
    go.M[0] = nA; go.M[1] = nR; go.aTiles = aTiles;

    // merged attention: role 0 = atoms->residues, role 1 = residues->atoms
    AArgs aa = {};
    aa.Q[0] = pAq; aa.K[0] = pRk; aa.V[0] = pRv; aa.O[0] = pTA;
    aa.scQ[0] = lig; aa.scKV[0] = res;
    aa.Q[1] = pRq; aa.K[1] = pAk; aa.V[1] = pAv; aa.O[1] = pTR;
    aa.scQ[1] = res; aa.scKV[1] = lig;

    gemm_fused_kernel<1,3,1><<<dim3(4, totTiles), 256, GEMM_SMEM3>>>(gi);

    for (int it = 0; it < 3; it++) {
        gemm_fused_kernel<0,1,2><<<dim3(6, totTiles), 256, GEMM_SMEM0>>>(gq);

        attn_mma_kernel<<<dim3(256, 9), 256, ATT_SMEM>>>(aa);

        gemm_fused_kernel<2,1,1><<<dim3(4, totTiles), 256, GEMM_SMEM1>>>(go);
    }

    copy_out_kernel<<<1024, 256>>>((float*)d_out, nA, nR);
}

// round 12
// speedup vs baseline: 1.3608x; 1.0561x over previous
#include <cuda_runtime.h>
#include <cstdint>

#define DD 256
#define NA_MAX (64*256)
#define NR_MAX (512*256)

// ---------------- scratch state (device globals; no allocation) ----------------
__device__ __align__(16) float gA  [NA_MAX*DD];   // state raw fp32
__device__ __align__(16) float gR  [NR_MAX*DD];
__device__ __align__(16) float gAt [NA_MAX*DD];   // state tf32-rounded (GEMM X input)
__device__ __align__(16) float gRt [NR_MAX*DD];
__device__ __align__(16) float gAq[NA_MAX*DD];    // QKV outputs: stored tf32-rounded
__device__ __align__(16) float gAk[NA_MAX*DD];
__device__ __align__(16) float gAv[NA_MAX*DD];
__device__ __align__(16) float gRq[NR_MAX*DD];
__device__ __align__(16) float gRk[NR_MAX*DD];
__device__ __align__(16) float gRv[NR_MAX*DD];
__device__ __align__(16) float gTA[NA_MAX*DD];    // attn out, stored tf32-rounded
__device__ __align__(16) float gTR[NR_MAX*DD];
__device__ __align__(16) float gWp [10*DD*DD*2];  // weights: fragment-major hi/lo (3x path)
__device__ __align__(16) float gWp1[10*DD*DD];    // weights: ldsm-packed hi only (1x path)
__device__ float gInvA[NA_MAX];
__device__ float gInvR[NR_MAX];

__device__ __forceinline__ float leaky_f(float x) { return x >= 0.f ? x : 0.1f * x; }
__device__ __forceinline__ float sigmoid_f(float x) {
    return __fdividef(1.f, 1.f + __expf(-x));
}
__device__ __forceinline__ float to_tf32(float x) {
    uint32_t u;
    asm("cvt.rna.tf32.f32 %0, %1;" : "=r"(u) : "f"(x));
    return __uint_as_float(u);
}
__device__ __forceinline__ void split_tf32(float x, float& hi, float& lo) {
    uint32_t u;
    asm("cvt.rna.tf32.f32 %0, %1;" : "=r"(u) : "f"(x));
    hi = __uint_as_float(u);
    float r = x - hi;
    uint32_t v;
    asm("cvt.rna.tf32.f32 %0, %1;" : "=r"(v) : "f"(r));
    lo = __uint_as_float(v);
}
__device__ __forceinline__ void mma_tf32(float* d, const uint32_t* a, const uint32_t* b) {
    asm volatile(
        "mma.sync.aligned.m16n8k8.row.col.f32.tf32.tf32.f32 "
        "{%0,%1,%2,%3}, {%4,%5,%6,%7}, {%8,%9}, {%0,%1,%2,%3};\n"
        : "+f"(d[0]), "+f"(d[1]), "+f"(d[2]), "+f"(d[3])
        : "r"(a[0]), "r"(a[1]), "r"(a[2]), "r"(a[3]), "r"(b[0]), "r"(b[1]));
}
__device__ __forceinline__ void ldsm_x4(uint32_t* r, uint32_t a) {
    asm volatile("ldmatrix.sync.aligned.m8n8.x4.shared.b16 {%0,%1,%2,%3}, [%4];"
        : "=r"(r[0]), "=r"(r[1]), "=r"(r[2]), "=r"(r[3]) : "r"(a));
}
__device__ __forceinline__ uint32_t smem_u32(const void* p) {
    return (uint32_t)__cvta_generic_to_shared(p);
}
__device__ __forceinline__ void cp16(uint32_t s, const void* g) {
    asm volatile("cp.async.cg.shared.global [%0], [%1], 16;\n" :: "r"(s), "l"(g));
}
__device__ __forceinline__ void cp_commit() { asm volatile("cp.async.commit_group;\n"); }
template <int N> __device__ __forceinline__ void cp_wait() {
    asm volatile("cp.async.wait_group %0;\n" :: "n"(N));
}

// ---------------- per-row 1/count scales ----------------
__global__ void fill_inv_kernel(const int* __restrict__ lig, const int* __restrict__ res) {
    int b = blockIdx.x;
    int as = lig[2*b], ac = lig[2*b+1];
    int rs = res[2*b], rc = res[2*b+1];
    float ia = 1.f / (float)rc;
    float ir = 1.f / (float)ac;
    for (int i = threadIdx.x; i < ac; i += blockDim.x) gInvA[as + i] = ia;
    for (int i = threadIdx.x; i < rc; i += blockDim.x) gInvR[rs + i] = ir;
}

// ---------------- weight presplit + permute ----------------
// 3x layout (gWp) unchanged: chunk 4096 floats, ((kk*8+nf8)*32+lane)*4 + {bh0,bh1,bl0,bl1}
// 1x layout (gWp1) ldsm-packed: chunk 2048 floats,
//   (kk*4 + nf8/2)*128 + ((nf8&1)*2 + khalf)*32 + lane
struct WIn { const float* w[10]; };
__global__ void presplit_w_kernel(WIn win, float* __restrict__ wp, float* __restrict__ wp1) {
    int i = blockIdx.x * 256 + threadIdx.x;
    if (i >= 10 * DD * DD) return;
    int s = i >> 16, rem = i & 65535;
    int k = rem >> 8, n = rem & 255;
    float h, l;
    split_tf32(win.w[s][rem], h, l);
    int coltile = n >> 6, nf8 = (n >> 3) & 7, lq = n & 7;
    int ktile = k >> 5, kk = (k >> 3) & 3, lr = k & 3, khalf = (k >> 2) & 1;
    int lane = lq * 4 + lr;
    int chunk = (s * 4 + coltile) * 8 + ktile;
    int fr = (kk * 8 + nf8) * 32 + lane;
    size_t b3 = (size_t)chunk * 4096 + (size_t)fr * 4;
    wp[b3 + khalf] = h;
    wp[b3 + 2 + khalf] = l;
    size_t b1 = (size_t)chunk * 2048
              + (size_t)((kk * 4 + (nf8 >> 1)) * 128 + ((nf8 & 1) * 2 + khalf) * 32 + lane);
    wp1[b1] = h;
}

// ---------------- fused tf32 pipelined GEMM (PREC 1|3, NT coltiles, 2-stage) ----------------
// MODE 0: C = tf32(XW) ; 1: C = leaky(XW) (+Ct rounded) ; 2: C = leaky(XW)*scale+base (+Ct)
struct GArgs {
    const float* X[2];
    const float* Wp[2][3];
    float*       C[2][3];
    float*       Ct[2];
    const float* scale[2];
    const float* base[2];
    int M[2];
    int aTiles;
};

#define GX_STR 36
#define GA_FLOATS (128*GX_STR)             // 4608

template <int BKT1, int NT>
__device__ __forceinline__ void gemm_stage(const float* X, const float* Wb,
                                           float* sXb, float* sBb,
                                           int row0, int M, int t, int tid)
{
    const int k0 = t * 32;
    #pragma unroll
    for (int j = 0; j < 4; j++) {
        int idx = tid + 256 * j;
        int row = idx >> 3, ch = idx & 7;
        int grow = row0 + row; if (grow > M - 1) grow = M - 1;   // clamp: garbage rows never stored
        cp16(smem_u32(sXb + row * GX_STR + ch * 4), X + (size_t)grow * DD + k0 + ch * 4);
    }
    #pragma unroll
    for (int ct = 0; ct < NT; ct++) {
        const float* src = Wb + (size_t)(ct * 8 + t) * BKT1;
        #pragma unroll
        for (int j = 0; j < BKT1 / 1024; j++)
            cp16(smem_u32(sBb + ct * BKT1 + (tid + 256 * j) * 4), src + (size_t)(tid + 256 * j) * 4);
    }
}

template <int MODE, int PREC, int NT>
__global__ void __launch_bounds__(256, (PREC == 1 && NT == 1) ? 3 : 2) gemm_fused_kernel(GArgs g)
{
    constexpr int BKT1 = (PREC == 3) ? 4096 : 2048;
    constexpr int BKT = NT * BKT1;
    constexpr int STAGE = GA_FLOATS + BKT;
    constexpr int NF = 4 * NT;
    constexpr int CGRP = 4 / NT;
    extern __shared__ float smf[];

    const int side = (blockIdx.y >= g.aTiles) ? 1 : 0;
    const int rt = side ? blockIdx.y - g.aTiles : blockIdx.y;
    const int w = blockIdx.x / CGRP;
    const int cg = blockIdx.x % CGRP;
    const int col0 = cg * (64 * NT);
    const int M = g.M[side];
    const int row0 = rt * 128;

    const float* X = g.X[side];
    const float* Wb = g.Wp[side][w] + (size_t)(cg * NT) * (8 * BKT1);
    float* C = g.C[side][w];

    const int tid = threadIdx.x, lane = tid & 31, warp = tid >> 5;
    const int wm = warp >> 1, wn = warp & 1;
    const int lq = lane >> 2, lr = lane & 3;

    float* sX[2] = { smf,             smf + STAGE };
    float* sB[2] = { smf + GA_FLOATS, smf + STAGE + GA_FLOATS };

    float acc[2][NF][4] = {};

    const int grp = lane >> 3, rr8 = lane & 7;
    const int arow_off = (grp & 1) * 8 + rr8;
    const int acol0 = (grp >> 1) * 4;
    const int bl_off = (lane >> 3) * 32 + (lane & 7) * 4;   // ldsm-B per-lane offset (floats)

    gemm_stage<BKT1, NT>(X, Wb, sX[0], sB[0], row0, M, 0, tid);
    cp_commit();

    for (int t = 0; t < 8; t++) {
        int buf = t & 1;
        if (t < 7) {
            gemm_stage<BKT1, NT>(X, Wb, sX[buf ^ 1], sB[buf ^ 1], row0, M, t + 1, tid);
            cp_commit();
            cp_wait<1>();
        } else {
            cp_wait<0>();
        }
        __syncthreads();

        #pragma unroll
        for (int kk = 0; kk < 4; kk++) {
            uint32_t ah[2][4], al[2][4];
            if (PREC == 1) {
                #pragma unroll
                for (int mf = 0; mf < 2; mf++) {
                    uint32_t addr = smem_u32(sX[buf] + (wm * 32 + mf * 16 + arow_off) * GX_STR
                                             + kk * 8 + acol0);
                    ldsm_x4(ah[mf], addr);
                }
            } else {
                #pragma unroll
                for (int mf = 0; mf < 2; mf++) {
                    const float* xb = sX[buf] + (wm * 32 + mf * 16 + lq) * GX_STR + kk * 8 + lr;
                    float raw[4];
                    raw[0] = xb[0]; raw[1] = xb[8 * GX_STR];
                    raw[2] = xb[4]; raw[3] = xb[8 * GX_STR + 4];
                    #pragma unroll
                    for (int e = 0; e < 4; e++) {
                        float h, l;
                        split_tf32(raw[e], h, l);
                        ah[mf][e] = __float_as_uint(h);
                        al[mf][e] = __float_as_uint(l);
                    }
                }
            }
            #pragma unroll
            for (int ct = 0; ct < NT; ct++) {
                if (PREC == 3) {
                    #pragma unroll
                    for (int nfi = 0; nfi < 4; nfi++) {
                        float4 bv = *(const float4*)(sB[buf] + ct * BKT1
                                     + (size_t)((kk * 8 + wn * 4 + nfi) * 32 + lane) * 4);
                        const uint32_t* bq = (const uint32_t*)&bv;
                        uint32_t bh[2] = { bq[0], bq[1] };
                        uint32_t bl[2] = { bq[2], bq[3] };
                        #pragma unroll
                        for (int mf = 0; mf < 2; mf++) {
                            mma_tf32(acc[mf][ct * 4 + nfi], al[mf], bh);
                            mma_tf32(acc[mf][ct * 4 + nfi], ah[mf], bl);
                            mma_tf32(acc[mf][ct * 4 + nfi], ah[mf], bh);
                        }
                    }
                } else {
                    uint32_t br0[4], br1[4];
                    ldsm_x4(br0, smem_u32(sB[buf] + ct * BKT1
                                          + (kk * 4 + wn * 2 + 0) * 128 + bl_off));
                    ldsm_x4(br1, smem_u32(sB[buf] + ct * BKT1
                                          + (kk * 4 + wn * 2 + 1) * 128 + bl_off));
                    #pragma unroll
                    for (int nfi = 0; nfi < 4; nfi++) {
                        const uint32_t* src = (nfi < 2) ? br0 : br1;
                        uint32_t bh[2] = { src[(nfi & 1) * 2], src[(nfi & 1) * 2 + 1] };
                        #pragma unroll
                        for (int mf = 0; mf < 2; mf++)
                            mma_tf32(acc[mf][ct * 4 + nfi], ah[mf], bh);
                    }
                }
            }
        }
        __syncthreads();
    }

    // ---- epilogue ----
    float* Ct = (MODE != 0) ? g.Ct[side] : nullptr;
    #pragma unroll
    for (int mf = 0; mf < 2; mf++) {
        #pragma unroll
        for (int i = 0; i < 4; i++) {
            int r = row0 + wm * 32 + mf * 16 + lq + ((i >= 2) ? 8 : 0);
            if (r >= M) continue;
            float sc = (MODE == 2) ? g.scale[side][r] : 0.f;
            #pragma unroll
            for (int nf = 0; nf < NF; nf++) {
                int c = col0 + (nf >> 2) * 64 + wn * 32 + (nf & 3) * 8 + lr * 2 + (i & 1);
                float v = acc[mf][nf][i];
                if (MODE == 0) {
                    C[(size_t)r * DD + c] = to_tf32(v);   // consumer (attention) rounds anyway
                } else {
                    if (MODE == 1) v = leaky_f(v);
                    if (MODE == 2) v = leaky_f(v) * sc + g.base[side][(size_t)r * DD + c];
                    C[(size_t)r * DD + c] = v;
                    Ct[(size_t)r * DD + c] = to_tf32(v);
                }
            }
        }
    }
}

#define GEMM_SMEM0 (2*(GA_FLOATS + 2*2048)*4)  // 69632 B  (MODE0, PREC1, NT2)
#define GEMM_SMEM3 (2*(GA_FLOATS + 4096)*4)    // 69632 B  (init, PREC3, NT1)
#define GEMM_SMEM1 (2*(GA_FLOATS + 2048)*4)    // 53248 B  (out, PREC1, NT1)

// ---------------- merged mma sigmoid attention (64-row KV tiles, ragged-aware skips) ----------------
// grid (256, 9): y==0 -> atoms attend to residues; y>=1 -> residues chunk (y-1) attend to atoms.
#define K_STR 260
#define V_STR 264
#define S_STR 68
#define ATT_K (64*K_STR)                    // 16640 (Q region size)
#define ATT_V (ATT_K + 64*K_STR)            // 33280
#define ATT_S (ATT_V + 64*V_STR)            // 50176
#define ATT_SMEM ((ATT_S + 64*S_STR)*4)     // 218112 B

struct AArgs {
    const float* Q[2];
    const float* K[2];
    const float* V[2];
    float*       O[2];
    const int*   scQ[2];
    const int*   scKV[2];
};

__device__ __forceinline__ void attn_stage64(const float* G, float* sdst, int str,
                                             size_t base0, int r0, int rmax, int rlim, int tid)
{
    #pragma unroll
    for (int i = 0; i < 16; i++) {
        int idx = tid + 256 * i;
        int row = idx >> 6, ch = idx & 63;
        if (row >= rlim) continue;
        int gr = r0 + row; if (gr > rmax) gr = rmax;   // clamp: masked/never-stored later
        cp16(smem_u32(sdst + row * str + ch * 4), G + (base0 + gr) * DD + ch * 4);
    }
}

__global__ void attn_mma_kernel(AArgs aa)
{
    extern __shared__ float smf[];
    float* sQ = smf;
    float* sK = smf + ATT_K;
    float* sV = smf + ATT_V;
    float* sS = smf + ATT_S;

    const int role = (blockIdx.y == 0) ? 0 : 1;
    const int chunk = (blockIdx.y == 0) ? 0 : (int)blockIdx.y - 1;
    const float* Q = aa.Q[role];
    const float* K = aa.K[role];
    const float* V = aa.V[role];
    float* O = aa.O[role];

    const int b = blockIdx.x;
    const int qs0 = aa.scQ[role][2*b], qc = aa.scQ[role][2*b+1];
    const int kv0i = aa.scKV[role][2*b], kvc = aa.scKV[role][2*b+1];
    const int qbeg = chunk * 64;
    if (qbeg >= qc) return;
    const int qcnt = (qc - qbeg < 64) ? (qc - qbeg) : 64;

    const int tid = threadIdx.x, lane = tid & 31, warp = tid >> 5;
    const int lq = lane >> 2, lr = lane & 3;
    const int grp = lane >> 3, rr8 = lane & 7;
    const int arow_off = (grp & 1) * 8 + rr8;
    const int acol0 = (grp >> 1) * 4;

    // first-tile limits
    int k0lim = (kvc < 64) ? kvc : 64;
    int nlim0 = ((k0lim + 7) >> 3) * 8;

    // prologue: stage Q + K0 (group), then V0 (group)
    attn_stage64(Q, sQ, K_STR, (size_t)qs0, qbeg, qc - 1, qcnt, tid);
    attn_stage64(K, sK, K_STR, (size_t)kv0i, 0, kvc - 1, nlim0, tid);
    cp_commit();
    attn_stage64(V, sV, V_STR, (size_t)kv0i, 0, kvc - 1, nlim0, tid);
    cp_commit();

    float o[4][4][4] = {};
    const int nT = (kvc + 63) >> 6;

    for (int t = 0; t < nT; t++) {
        cp_wait<1>();            // K[t] (and Q at t=0) complete; V[t] may be in flight
        __syncthreads();
        int klim = kvc - t * 64; if (klim > 64) klim = 64;
        int klim8 = (klim + 7) >> 3;
        int nlim = klim8 * 8;

        // ---- phase S: 64x64 scores, K=256; 8 warps as 2(m) x 4(n), warp tile 32x16 ----
        {
            const int wmS = warp >> 2, wnS = warp & 3;
            const int m0 = wmS * 32, n0 = wnS * 16;
            if (m0 < qcnt && n0 < nlim) {
                float s[2][2][4] = {};
                #pragma unroll 4
                for (int kk = 0; kk < 32; kk++) {
                    uint32_t a[2][4];
                    ldsm_x4(a[0], smem_u32(sQ + (m0 + arow_off) * K_STR + kk * 8 + acol0));
                    ldsm_x4(a[1], smem_u32(sQ + (m0 + 16 + arow_off) * K_STR + kk * 8 + acol0));
                    uint32_t kr[4];
                    ldsm_x4(kr, smem_u32(sK + (n0 + arow_off) * K_STR + kk * 8 + acol0));
                    uint32_t b0[2] = { kr[0], kr[2] };
                    uint32_t b1[2] = { kr[1], kr[3] };
                    mma_tf32(s[0][0], a[0], b0); mma_tf32(s[0][1], a[0], b1);
                    mma_tf32(s[1][0], a[1], b0); mma_tf32(s[1][1], a[1], b1);
                }
                #pragma unroll
                for (int mf = 0; mf < 2; mf++)
                    #pragma unroll
                    for (int nf = 0; nf < 2; nf++)
                        #pragma unroll
                        for (int e = 0; e < 4; e++) {
                            int row = m0 + mf * 16 + lq + ((e >= 2) ? 8 : 0);
                            int col = n0 + nf * 8 + lr * 2 + (e & 1);
                            float v = (col < klim) ? sigmoid_f(s[mf][nf][e]) : 0.f;
                            sS[row * S_STR + col] = to_tf32(v);
                        }
            }
        }
        __syncthreads();         // sS ready; sK free
        if (t + 1 < nT) {
            int rem = kvc - (t + 1) * 64; if (rem > 64) rem = 64;
            int nl2 = ((rem + 7) >> 3) * 8;
            attn_stage64(K, sK, K_STR, (size_t)kv0i, (t + 1) * 64, kvc - 1, nl2, tid);
        }
        cp_commit();             // group K[t+1] (possibly empty)
        cp_wait<1>();            // V[t] complete (pending: K[t+1])
        __syncthreads();

        // ---- phase PV: O += S @ V; each warp owns 32 feature cols; ks 0..klim8-1 ----
        {
            const int n0v = warp * 32;
            for (int ks = 0; ks < klim8; ks++) {
                uint32_t a[4][4], bb[4][2];
                #pragma unroll
                for (int mf = 0; mf < 4; mf++)
                    if (mf * 16 < qcnt)
                        ldsm_x4(a[mf], smem_u32(sS + (mf * 16 + arow_off) * S_STR + ks * 8 + acol0));
                #pragma unroll
                for (int nf = 0; nf < 4; nf++) {
                    const float* vp = sV + (ks * 8 + lr) * V_STR + n0v + nf * 8 + lq;
                    bb[nf][0] = __float_as_uint(vp[0]);
                    bb[nf][1] = __float_as_uint(vp[4 * V_STR]);
                }
                #pragma unroll
                for (int mf = 0; mf < 4; mf++)
                    if (mf * 16 < qcnt)
                        #pragma unroll
                        for (int nf = 0; nf < 4; nf++)
                            mma_tf32(o[mf][nf], a[mf], bb[nf]);
            }
        }
        __syncthreads();         // sV, sS free
        if (t + 1 < nT) {
            int rem = kvc - (t + 1) * 64; if (rem > 64) rem = 64;
            int nl2 = ((rem + 7) >> 3) * 8;
            attn_stage64(V, sV, V_STR, (size_t)kv0i, (t + 1) * 64, kvc - 1, nl2, tid);
        }
        cp_commit();             // group V[t+1] (possibly empty)
    }

    // ---- store O tf32-rounded (only consumer is the 1x output GEMM) ----
    const int n0v = warp * 32;
    float* Obase = O + (size_t)(qs0 + qbeg) * DD;
    #pragma unroll
    for (int mf = 0; mf < 4; mf++)
        #pragma unroll
        for (int e = 0; e < 4; e++) {
            int row = mf * 16 + lq + ((e >= 2) ? 8 : 0);
            if (row >= qcnt) continue;
            #pragma unroll
            for (int nf = 0; nf < 4; nf++) {
                int col = n0v + nf * 8 + lr * 2 + (e & 1);
                Obase[(size_t)row * DD + col] = to_tf32(o[mf][nf][e]);
            }
        }
}

// ---------------- final output: concat(A_flat, R_flat) ----------------
__global__ void copy_out_kernel(float* __restrict__ out, int nA, int nR) {
    size_t na4 = (size_t)nA * DD / 4;
    size_t tot = (size_t)(nA + nR) * DD / 4;
    const float4* a4 = (const float4*)gA;
    const float4* r4 = (const float4*)gR;
    for (size_t i = blockIdx.x * (size_t)blockDim.x + threadIdx.x; i < tot;
         i += (size_t)gridDim.x * blockDim.x) {
        ((float4*)out)[i] = (i < na4) ? a4[i] : r4[i - na4];
    }
}

// ---------------- host launch ----------------
extern "C" void kernel_launch(void* const* d_in, const int* in_sizes, int n_in,
                              void* d_out, int out_size) {
    const float* fatoms = (const float*)d_in[0];
    const float* fres   = (const float*)d_in[1];
    const int* lig = (const int*)d_in[12];
    const int* res = (const int*)d_in[13];

    int nA = in_sizes[0] / DD;
    int nR = in_sizes[1] / DD;

    float *pA, *pR, *pAt, *pRt, *pAq, *pAk, *pAv, *pRq, *pRk, *pRv, *pTA, *pTR;
    float *pWp, *pWp1, *pInvA, *pInvR;
    cudaGetSymbolAddress((void**)&pA,  gA);
    cudaGetSymbolAddress((void**)&pR,  gR);
    cudaGetSymbolAddress((void**)&pAt, gAt);
    cudaGetSymbolAddress((void**)&pRt, gRt);
    cudaGetSymbolAddress((void**)&pAq, gAq);
    cudaGetSymbolAddress((void**)&pAk, gAk);
    cudaGetSymbolAddress((void**)&pAv, gAv);
    cudaGetSymbolAddress((void**)&pRq, gRq);
    cudaGetSymbolAddress((void**)&pRk, gRk);
    cudaGetSymbolAddress((void**)&pRv, gRv);
    cudaGetSymbolAddress((void**)&pTA, gTA);
    cudaGetSymbolAddress((void**)&pTR, gTR);
    cudaGetSymbolAddress((void**)&pWp, gWp);
    cudaGetSymbolAddress((void**)&pWp1, gWp1);
    cudaGetSymbolAddress((void**)&pInvA, gInvA);
    cudaGetSymbolAddress((void**)&pInvR, gInvR);

    cudaFuncSetAttribute(gemm_fused_kernel<1,3,1>, cudaFuncAttributeMaxDynamicSharedMemorySize, GEMM_SMEM3);
    cudaFuncSetAttribute(gemm_fused_kernel<0,1,2>, cudaFuncAttributeMaxDynamicSharedMemorySize, GEMM_SMEM0);
    cudaFuncSetAttribute(gemm_fused_kernel<2,1,1>, cudaFuncAttributeMaxDynamicSharedMemorySize, GEMM_SMEM1);
    cudaFuncSetAttribute(attn_mma_kernel, cudaFuncAttributeMaxDynamicSharedMemorySize, ATT_SMEM);

    // weight slot order: 0=W_lig_t 1=WQl 2=WKl 3=WVl 4=WOl | 5=W_res_t 6=WQr 7=WKr 8=WVr 9=WOr
    WIn win;
    win.w[0] = (const float*)d_in[2];
    win.w[1] = (const float*)d_in[4];
    win.w[2] = (const float*)d_in[5];
    win.w[3] = (const float*)d_in[6];
    win.w[4] = (const float*)d_in[7];
    win.w[5] = (const float*)d_in[3];
    win.w[6] = (const float*)d_in[8];
    win.w[7] = (const float*)d_in[9];
    win.w[8] = (const float*)d_in[10];
    win.w[9] = (const float*)d_in[11];

    const int aTiles = (nA + 127) / 128;
    const int rTiles = (nR + 127) / 128;
    const int totTiles = aTiles + rTiles;
    const int WSLOT3 = DD * DD * 2;
    const int WSLOT1 = DD * DD;

    fill_inv_kernel<<<256, 256>>>(lig, res);
    presplit_w_kernel<<<(10 * DD * DD + 255) / 256, 256>>>(win, pWp, pWp1);

    // init transforms (3x): A0 = leaky(fatoms@W_lig_t), R0 = leaky(fres@W_res_t)
    GArgs gi = {};
    gi.X[0] = fatoms; gi.X[1] = fres;
    gi.Wp[0][0] = pWp + 0 * WSLOT3; gi.Wp[1][0] = pWp + 5 * WSLOT3;
    gi.C[0][0] = pA; gi.C[1][0] = pR;
    gi.Ct[0] = pAt; gi.Ct[1] = pRt;
    gi.M[0] = nA; gi.M[1] = nR; gi.aTiles = aTiles;

    // fused QKV projections (1x, NT=2, pre-rounded X, rounded outputs)
    GArgs gq = {};
    gq.X[0] = pAt; gq.X[1] = pRt;
    for (int j = 0; j < 3; j++) {
        gq.Wp[0][j] = pWp1 + (1 + j) * WSLOT1;
        gq.Wp[1][j] = pWp1 + (6 + j) * WSLOT1;
    }
    gq.C[0][0] = pAq; gq.C[0][1] = pAk; gq.C[0][2] = pAv;
    gq.C[1][0] = pRq; gq.C[1][1] = pRk; gq.C[1][2] = pRv;
    gq.M[0] = nA; gq.M[1] = nR; gq.aTiles = aTiles;

    // output GEMMs (1x): A = leaky(TA@WOl)*invA + A ; R = leaky(TR@WOr)*invR + R
    GArgs go = {};
    go.X[0] = pTA; go.X[1] = pTR;          // already tf32-rounded by attention store
    go.Wp[0][0] = pWp1 + 4 * WSLOT1; go.Wp[1][0] = pWp1 + 9 * WSLOT1;
    go.C[0][0] = pA; go.C[1][0] = pR;
    go.Ct[0] = pAt; go.Ct[1] = pRt;
    go.scale[0] = pInvA; go.scale[1] = pInvR;
    go.base[0] = pA; go.base[1] = pR;
    go.M[0] = nA; go.M[1] = nR; go.aTiles = aTiles;

    // merged attention: role 0 = atoms->residues, role 1 = residues->atoms
    AArgs aa = {};
    aa.Q[0] = pAq; aa.K[0] = pRk; aa.V[0] = pRv; aa.O[0] = pTA;
    aa.scQ[0] = lig; aa.scKV[0] = res;
    aa.Q[1] = pRq; aa.K[1] = pAk; aa.V[1] = pAv; aa.O[1] = pTR;
    aa.scQ[1] = res; aa.scKV[1] = lig;

    gemm_fused_kernel<1,3,1><<<dim3(4, totTiles), 256, GEMM_SMEM3>>>(gi);

    for (int it = 0; it < 3; it++) {
        gemm_fused_kernel<0,1,2><<<dim3(6, totTiles), 256, GEMM_SMEM0>>>(gq);

        attn_mma_kernel<<<dim3(256, 9), 256, ATT_SMEM>>>(aa);

        gemm_fused_kernel<2,1,1><<<dim3(4, totTiles), 256, GEMM_SMEM1>>>(go);
    }

    copy_out_kernel<<<1024, 256>>>((float*)d_out, nA, nR);
}

// round 13
// speedup vs baseline: 1.3624x; 1.0011x over previous
#include <cuda_runtime.h>
#include <cstdint>

#define DD 256
#define NA_MAX (64*256)
#define NR_MAX (512*256)

// ---------------- scratch state (device globals; no allocation) ----------------
__device__ __align__(16) float gA  [NA_MAX*DD];   // state raw fp32
__device__ __align__(16) float gR  [NR_MAX*DD];
__device__ __align__(16) float gAt [NA_MAX*DD];   // state tf32-rounded (GEMM X input)
__device__ __align__(16) float gRt [NR_MAX*DD];
__device__ __align__(16) float gAq[NA_MAX*DD];    // QKV outputs: stored tf32-rounded
__device__ __align__(16) float gAk[NA_MAX*DD];
__device__ __align__(16) float gAv[NA_MAX*DD];
__device__ __align__(16) float gRq[NR_MAX*DD];
__device__ __align__(16) float gRk[NR_MAX*DD];
__device__ __align__(16) float gRv[NR_MAX*DD];
__device__ __align__(16) float gTA[NA_MAX*DD];    // attn out, stored tf32-rounded
__device__ __align__(16) float gTR[NR_MAX*DD];
__device__ __align__(16) float gWp [10*DD*DD*2];  // weights: fragment-major hi/lo (3x path)
__device__ __align__(16) float gWp1[10*DD*DD];    // weights: ldsm-packed hi only (1x path)
__device__ float gInvA[NA_MAX];
__device__ float gInvR[NR_MAX];

__device__ __forceinline__ float leaky_f(float x) { return x >= 0.f ? x : 0.1f * x; }
__device__ __forceinline__ float sigmoid_f(float x) {
    return __fdividef(1.f, 1.f + __expf(-x));
}
__device__ __forceinline__ float to_tf32(float x) {
    uint32_t u;
    asm("cvt.rna.tf32.f32 %0, %1;" : "=r"(u) : "f"(x));
    return __uint_as_float(u);
}
__device__ __forceinline__ void split_tf32(float x, float& hi, float& lo) {
    uint32_t u;
    asm("cvt.rna.tf32.f32 %0, %1;" : "=r"(u) : "f"(x));
    hi = __uint_as_float(u);
    float r = x - hi;
    uint32_t v;
    asm("cvt.rna.tf32.f32 %0, %1;" : "=r"(v) : "f"(r));
    lo = __uint_as_float(v);
}
__device__ __forceinline__ void mma_tf32(float* d, const uint32_t* a, const uint32_t* b) {
    asm volatile(
        "mma.sync.aligned.m16n8k8.row.col.f32.tf32.tf32.f32 "
        "{%0,%1,%2,%3}, {%4,%5,%6,%7}, {%8,%9}, {%0,%1,%2,%3};\n"
        : "+f"(d[0]), "+f"(d[1]), "+f"(d[2]), "+f"(d[3])
        : "r"(a[0]), "r"(a[1]), "r"(a[2]), "r"(a[3]), "r"(b[0]), "r"(b[1]));
}
__device__ __forceinline__ void ldsm_x4(uint32_t* r, uint32_t a) {
    asm volatile("ldmatrix.sync.aligned.m8n8.x4.shared.b16 {%0,%1,%2,%3}, [%4];"
        : "=r"(r[0]), "=r"(r[1]), "=r"(r[2]), "=r"(r[3]) : "r"(a));
}
__device__ __forceinline__ uint32_t smem_u32(const void* p) {
    return (uint32_t)__cvta_generic_to_shared(p);
}
__device__ __forceinline__ void cp16(uint32_t s, const void* g) {
    asm volatile("cp.async.cg.shared.global [%0], [%1], 16;\n" :: "r"(s), "l"(g));
}
__device__ __forceinline__ void cp_commit() { asm volatile("cp.async.commit_group;\n"); }
template <int N> __device__ __forceinline__ void cp_wait() {
    asm volatile("cp.async.wait_group %0;\n" :: "n"(N));
}

// ---------------- per-row 1/count scales ----------------
__global__ void fill_inv_kernel(const int* __restrict__ lig, const int* __restrict__ res) {
    int b = blockIdx.x;
    int as = lig[2*b], ac = lig[2*b+1];
    int rs = res[2*b], rc = res[2*b+1];
    float ia = 1.f / (float)rc;
    float ir = 1.f / (float)ac;
    for (int i = threadIdx.x; i < ac; i += blockDim.x) gInvA[as + i] = ia;
    for (int i = threadIdx.x; i < rc; i += blockDim.x) gInvR[rs + i] = ir;
}

// ---------------- weight presplit + permute ----------------
// 3x layout (gWp): chunk 4096 floats, ((kk*8+nf8)*32+lane)*4 + {bh0,bh1,bl0,bl1}
// 1x layout (gWp1) ldsm-packed: chunk 2048 floats,
//   (kk*4 + nf8/2)*128 + ((nf8&1)*2 + khalf)*32 + lane
struct WIn { const float* w[10]; };
__global__ void presplit_w_kernel(WIn win, float* __restrict__ wp, float* __restrict__ wp1) {
    int i = blockIdx.x * 256 + threadIdx.x;
    if (i >= 10 * DD * DD) return;
    int s = i >> 16, rem = i & 65535;
    int k = rem >> 8, n = rem & 255;
    float h, l;
    split_tf32(win.w[s][rem], h, l);
    int coltile = n >> 6, nf8 = (n >> 3) & 7, lq = n & 7;
    int ktile = k >> 5, kk = (k >> 3) & 3, lr = k & 3, khalf = (k >> 2) & 1;
    int lane = lq * 4 + lr;
    int chunk = (s * 4 + coltile) * 8 + ktile;
    int fr = (kk * 8 + nf8) * 32 + lane;
    size_t b3 = (size_t)chunk * 4096 + (size_t)fr * 4;
    wp[b3 + khalf] = h;
    wp[b3 + 2 + khalf] = l;
    size_t b1 = (size_t)chunk * 2048
              + (size_t)((kk * 4 + (nf8 >> 1)) * 128 + ((nf8 & 1) * 2 + khalf) * 32 + lane);
    wp1[b1] = h;
}

// ---------------- fused tf32 pipelined GEMM (PREC 1|3, NT coltiles, 2-stage) ----------------
// MODE 0: C = tf32(XW) ; 1: C = leaky(XW) (+Ct rounded) ; 2: C = leaky(XW)*scale+base (+Ct)
struct GArgs {
    const float* X[2];
    const float* Wp[2][3];
    float*       C[2][3];
    float*       Ct[2];
    const float* scale[2];
    const float* base[2];
    int M[2];
    int aTiles;
};

#define GX_STR 36
#define GA_FLOATS (128*GX_STR)             // 4608

template <int BKT1, int NT>
__device__ __forceinline__ void gemm_stage(const float* X, const float* Wb,
                                           float* sXb, float* sBb,
                                           int row0, int M, int t, int tid)
{
    const int k0 = t * 32;
    #pragma unroll
    for (int j = 0; j < 4; j++) {
        int idx = tid + 256 * j;
        int row = idx >> 3, ch = idx & 7;
        int grow = row0 + row; if (grow > M - 1) grow = M - 1;   // clamp: garbage rows never stored
        cp16(smem_u32(sXb + row * GX_STR + ch * 4), X + (size_t)grow * DD + k0 + ch * 4);
    }
    #pragma unroll
    for (int ct = 0; ct < NT; ct++) {
        const float* src = Wb + (size_t)(ct * 8 + t) * BKT1;
        #pragma unroll
        for (int j = 0; j < BKT1 / 1024; j++)
            cp16(smem_u32(sBb + ct * BKT1 + (tid + 256 * j) * 4), src + (size_t)(tid + 256 * j) * 4);
    }
}

template <int MODE, int PREC, int NT>
__global__ void __launch_bounds__(256, (PREC == 1 && NT == 1) ? 3 : 2) gemm_fused_kernel(GArgs g)
{
    constexpr int BKT1 = (PREC == 3) ? 4096 : 2048;
    constexpr int BKT = NT * BKT1;
    constexpr int STAGE = GA_FLOATS + BKT;
    constexpr int NF = 4 * NT;
    constexpr int CGRP = 4 / NT;
    extern __shared__ float smf[];

    const int side = (blockIdx.y >= g.aTiles) ? 1 : 0;
    const int rt = side ? blockIdx.y - g.aTiles : blockIdx.y;
    const int w = blockIdx.x / CGRP;
    const int cg = blockIdx.x % CGRP;
    const int col0 = cg * (64 * NT);
    const int M = g.M[side];
    const int row0 = rt * 128;

    const float* X = g.X[side];
    const float* Wb = g.Wp[side][w] + (size_t)(cg * NT) * (8 * BKT1);
    float* C = g.C[side][w];

    const int tid = threadIdx.x, lane = tid & 31, warp = tid >> 5;
    const int wm = warp >> 1, wn = warp & 1;
    const int lq = lane >> 2, lr = lane & 3;

    float* sX[2] = { smf,             smf + STAGE };
    float* sB[2] = { smf + GA_FLOATS, smf + STAGE + GA_FLOATS };

    float acc[2][NF][4] = {};

    const int grp = lane >> 3, rr8 = lane & 7;
    const int arow_off = (grp & 1) * 8 + rr8;
    const int acol0 = (grp >> 1) * 4;
    const int bl_off = (lane >> 3) * 32 + (lane & 7) * 4;   // ldsm-B per-lane offset (floats)

    gemm_stage<BKT1, NT>(X, Wb, sX[0], sB[0], row0, M, 0, tid);
    cp_commit();

    for (int t = 0; t < 8; t++) {
        int buf = t & 1;
        if (t < 7) {
            gemm_stage<BKT1, NT>(X, Wb, sX[buf ^ 1], sB[buf ^ 1], row0, M, t + 1, tid);
            cp_commit();
            cp_wait<1>();
        } else {
            cp_wait<0>();
        }
        __syncthreads();

        #pragma unroll
        for (int kk = 0; kk < 4; kk++) {
            uint32_t ah[2][4], al[2][4];
            if (PREC == 1) {
                #pragma unroll
                for (int mf = 0; mf < 2; mf++) {
                    uint32_t addr = smem_u32(sX[buf] + (wm * 32 + mf * 16 + arow_off) * GX_STR
                                             + kk * 8 + acol0);
                    ldsm_x4(ah[mf], addr);
                }
            } else {
                #pragma unroll
                for (int mf = 0; mf < 2; mf++) {
                    const float* xb = sX[buf] + (wm * 32 + mf * 16 + lq) * GX_STR + kk * 8 + lr;
                    float raw[4];
                    raw[0] = xb[0]; raw[1] = xb[8 * GX_STR];
                    raw[2] = xb[4]; raw[3] = xb[8 * GX_STR + 4];
                    #pragma unroll
                    for (int e = 0; e < 4; e++) {
                        float h, l;
                        split_tf32(raw[e], h, l);
                        ah[mf][e] = __float_as_uint(h);
                        al[mf][e] = __float_as_uint(l);
                    }
                }
            }
            #pragma unroll
            for (int ct = 0; ct < NT; ct++) {
                if (PREC == 3) {
                    #pragma unroll
                    for (int nfi = 0; nfi < 4; nfi++) {
                        float4 bv = *(const float4*)(sB[buf] + ct * BKT1
                                     + (size_t)((kk * 8 + wn * 4 + nfi) * 32 + lane) * 4);
                        const uint32_t* bq = (const uint32_t*)&bv;
                        uint32_t bh[2] = { bq[0], bq[1] };
                        uint32_t bl[2] = { bq[2], bq[3] };
                        #pragma unroll
                        for (int mf = 0; mf < 2; mf++) {
                            mma_tf32(acc[mf][ct * 4 + nfi], al[mf], bh);
                            mma_tf32(acc[mf][ct * 4 + nfi], ah[mf], bl);
                            mma_tf32(acc[mf][ct * 4 + nfi], ah[mf], bh);
                        }
                    }
                } else {
                    uint32_t br0[4], br1[4];
                    ldsm_x4(br0, smem_u32(sB[buf] + ct * BKT1
                                          + (kk * 4 + wn * 2 + 0) * 128 + bl_off));
                    ldsm_x4(br1, smem_u32(sB[buf] + ct * BKT1
                                          + (kk * 4 + wn * 2 + 1) * 128 + bl_off));
                    #pragma unroll
                    for (int nfi = 0; nfi < 4; nfi++) {
                        const uint32_t* src = (nfi < 2) ? br0 : br1;
                        uint32_t bh[2] = { src[(nfi & 1) * 2], src[(nfi & 1) * 2 + 1] };
                        #pragma unroll
                        for (int mf = 0; mf < 2; mf++)
                            mma_tf32(acc[mf][ct * 4 + nfi], ah[mf], bh);
                    }
                }
            }
        }
        __syncthreads();
    }

    // ---- epilogue ----
    float* Ct = (MODE != 0) ? g.Ct[side] : nullptr;
    #pragma unroll
    for (int mf = 0; mf < 2; mf++) {
        #pragma unroll
        for (int i = 0; i < 4; i++) {
            int r = row0 + wm * 32 + mf * 16 + lq + ((i >= 2) ? 8 : 0);
            if (r >= M) continue;
            float sc = (MODE == 2) ? g.scale[side][r] : 0.f;
            #pragma unroll
            for (int nf = 0; nf < NF; nf++) {
                int c = col0 + (nf >> 2) * 64 + wn * 32 + (nf & 3) * 8 + lr * 2 + (i & 1);
                float v = acc[mf][nf][i];
                if (MODE == 0) {
                    C[(size_t)r * DD + c] = to_tf32(v);   // consumer (attention) rounds anyway
                } else {
                    if (MODE == 1) v = leaky_f(v);
                    if (MODE == 2) v = leaky_f(v) * sc + g.base[side][(size_t)r * DD + c];
                    C[(size_t)r * DD + c] = v;
                    Ct[(size_t)r * DD + c] = to_tf32(v);
                }
            }
        }
    }
}

#define GEMM_SMEM0 (2*(GA_FLOATS + 2*2048)*4)  // 69632 B  (PREC1, NT2)
#define GEMM_SMEM3 (2*(GA_FLOATS + 2*4096)*4)  // 102400 B (init, PREC3, NT2)

// ---------------- merged mma sigmoid attention (64-row KV tiles, ragged-aware skips) ----------------
// grid (256, 9): y==0 -> atoms attend to residues; y>=1 -> residues chunk (y-1) attend to atoms.
#define K_STR 260
#define V_STR 264
#define S_STR 68
#define ATT_K (64*K_STR)                    // 16640 (Q region size)
#define ATT_V (ATT_K + 64*K_STR)            // 33280
#define ATT_S (ATT_V + 64*V_STR)            // 50176
#define ATT_SMEM ((ATT_S + 64*S_STR)*4)     // 218112 B

struct AArgs {
    const float* Q[2];
    const float* K[2];
    const float* V[2];
    float*       O[2];
    const int*   scQ[2];
    const int*   scKV[2];
};

__device__ __forceinline__ void attn_stage64(const float* G, float* sdst, int str,
                                             size_t base0, int r0, int rmax, int rlim, int tid)
{
    #pragma unroll
    for (int i = 0; i < 16; i++) {
        int idx = tid + 256 * i;
        int row = idx >> 6, ch = idx & 63;
        if (row >= rlim) continue;
        int gr = r0 + row; if (gr > rmax) gr = rmax;   // clamp: masked/never-stored later
        cp16(smem_u32(sdst + row * str + ch * 4), G + (base0 + gr) * DD + ch * 4);
    }
}

__global__ void attn_mma_kernel(AArgs aa)
{
    extern __shared__ float smf[];
    float* sQ = smf;
    float* sK = smf + ATT_K;
    float* sV = smf + ATT_V;
    float* sS = smf + ATT_S;

    const int role = (blockIdx.y == 0) ? 0 : 1;
    const int chunk = (blockIdx.y == 0) ? 0 : (int)blockIdx.y - 1;
    const float* Q = aa.Q[role];
    const float* K = aa.K[role];
    const float* V = aa.V[role];
    float* O = aa.O[role];

    const int b = blockIdx.x;
    const int qs0 = aa.scQ[role][2*b], qc = aa.scQ[role][2*b+1];
    const int kv0i = aa.scKV[role][2*b], kvc = aa.scKV[role][2*b+1];
    const int qbeg = chunk * 64;
    if (qbeg >= qc) return;
    const int qcnt = (qc - qbeg < 64) ? (qc - qbeg) : 64;

    const int tid = threadIdx.x, lane = tid & 31, warp = tid >> 5;
    const int lq = lane >> 2, lr = lane & 3;
    const int grp = lane >> 3, rr8 = lane & 7;
    const int arow_off = (grp & 1) * 8 + rr8;
    const int acol0 = (grp >> 1) * 4;

    // first-tile limits
    int k0lim = (kvc < 64) ? kvc : 64;
    int nlim0 = ((k0lim + 7) >> 3) * 8;

    // prologue: stage Q + K0 (group), then V0 (group)
    attn_stage64(Q, sQ, K_STR, (size_t)qs0, qbeg, qc - 1, qcnt, tid);
    attn_stage64(K, sK, K_STR, (size_t)kv0i, 0, kvc - 1, nlim0, tid);
    cp_commit();
    attn_stage64(V, sV, V_STR, (size_t)kv0i, 0, kvc - 1, nlim0, tid);
    cp_commit();

    float o[4][4][4] = {};
    const int nT = (kvc + 63) >> 6;

    for (int t = 0; t < nT; t++) {
        cp_wait<1>();            // K[t] (and Q at t=0) complete; V[t] may be in flight
        __syncthreads();
        int klim = kvc - t * 64; if (klim > 64) klim = 64;
        int klim8 = (klim + 7) >> 3;
        int nlim = klim8 * 8;

        // ---- phase S: 64x64 scores, K=256; 8 warps as 2(m) x 4(n), warp tile 32x16 ----
        {
            const int wmS = warp >> 2, wnS = warp & 3;
            const int m0 = wmS * 32, n0 = wnS * 16;
            if (m0 < qcnt && n0 < nlim) {
                float s[2][2][4] = {};
                #pragma unroll 4
                for (int kk = 0; kk < 32; kk++) {
                    uint32_t a[2][4];
                    ldsm_x4(a[0], smem_u32(sQ + (m0 + arow_off) * K_STR + kk * 8 + acol0));
                    ldsm_x4(a[1], smem_u32(sQ + (m0 + 16 + arow_off) * K_STR + kk * 8 + acol0));
                    uint32_t kr[4];
                    ldsm_x4(kr, smem_u32(sK + (n0 + arow_off) * K_STR + kk * 8 + acol0));
                    uint32_t b0[2] = { kr[0], kr[2] };
                    uint32_t b1[2] = { kr[1], kr[3] };
                    mma_tf32(s[0][0], a[0], b0); mma_tf32(s[0][1], a[0], b1);
                    mma_tf32(s[1][0], a[1], b0); mma_tf32(s[1][1], a[1], b1);
                }
                #pragma unroll
                for (int mf = 0; mf < 2; mf++)
                    #pragma unroll
                    for (int nf = 0; nf < 2; nf++)
                        #pragma unroll
                        for (int e = 0; e < 4; e++) {
                            int row = m0 + mf * 16 + lq + ((e >= 2) ? 8 : 0);
                            int col = n0 + nf * 8 + lr * 2 + (e & 1);
                            float v = (col < klim) ? sigmoid_f(s[mf][nf][e]) : 0.f;
                            sS[row * S_STR + col] = to_tf32(v);
                        }
            }
        }
        __syncthreads();         // sS ready; sK free
        if (t + 1 < nT) {
            int rem = kvc - (t + 1) * 64; if (rem > 64) rem = 64;
            int nl2 = ((rem + 7) >> 3) * 8;
            attn_stage64(K, sK, K_STR, (size_t)kv0i, (t + 1) * 64, kvc - 1, nl2, tid);
        }
        cp_commit();             // group K[t+1] (possibly empty)
        cp_wait<1>();            // V[t] complete (pending: K[t+1])
        __syncthreads();

        // ---- phase PV: O += S @ V; each warp owns 32 feature cols; ks 0..klim8-1 ----
        {
            const int n0v = warp * 32;
            for (int ks = 0; ks < klim8; ks++) {
                uint32_t a[4][4], bb[4][2];
                #pragma unroll
                for (int mf = 0; mf < 4; mf++)
                    if (mf * 16 < qcnt)
                        ldsm_x4(a[mf], smem_u32(sS + (mf * 16 + arow_off) * S_STR + ks * 8 + acol0));
                #pragma unroll
                for (int nf = 0; nf < 4; nf++) {
                    const float* vp = sV + (ks * 8 + lr) * V_STR + n0v + nf * 8 + lq;
                    bb[nf][0] = __float_as_uint(vp[0]);
                    bb[nf][1] = __float_as_uint(vp[4 * V_STR]);
                }
                #pragma unroll
                for (int mf = 0; mf < 4; mf++)
                    if (mf * 16 < qcnt)
                        #pragma unroll
                        for (int nf = 0; nf < 4; nf++)
                            mma_tf32(o[mf][nf], a[mf], bb[nf]);
            }
        }
        __syncthreads();         // sV, sS free
        if (t + 1 < nT) {
            int rem = kvc - (t + 1) * 64; if (rem > 64) rem = 64;
            int nl2 = ((rem + 7) >> 3) * 8;
            attn_stage64(V, sV, V_STR, (size_t)kv0i, (t + 1) * 64, kvc - 1, nl2, tid);
        }
        cp_commit();             // group V[t+1] (possibly empty)
    }

    // ---- store O tf32-rounded (only consumer is the 1x output GEMM) ----
    const int n0v = warp * 32;
    float* Obase = O + (size_t)(qs0 + qbeg) * DD;
    #pragma unroll
    for (int mf = 0; mf < 4; mf++)
        #pragma unroll
        for (int e = 0; e < 4; e++) {
            int row = mf * 16 + lq + ((e >= 2) ? 8 : 0);
            if (row >= qcnt) continue;
            #pragma unroll
            for (int nf = 0; nf < 4; nf++) {
                int col = n0v + nf * 8 + lr * 2 + (e & 1);
                Obase[(size_t)row * DD + col] = to_tf32(o[mf][nf][e]);
            }
        }
}

// ---------------- host launch ----------------
extern "C" void kernel_launch(void* const* d_in, const int* in_sizes, int n_in,
                              void* d_out, int out_size) {
    const float* fatoms = (const float*)d_in[0];
    const float* fres   = (const float*)d_in[1];
    const int* lig = (const int*)d_in[12];
    const int* res = (const int*)d_in[13];

    int nA = in_sizes[0] / DD;
    int nR = in_sizes[1] / DD;

    float *pA, *pR, *pAt, *pRt, *pAq, *pAk, *pAv, *pRq, *pRk, *pRv, *pTA, *pTR;
    float *pWp, *pWp1, *pInvA, *pInvR;
    cudaGetSymbolAddress((void**)&pA,  gA);
    cudaGetSymbolAddress((void**)&pR,  gR);
    cudaGetSymbolAddress((void**)&pAt, gAt);
    cudaGetSymbolAddress((void**)&pRt, gRt);
    cudaGetSymbolAddress((void**)&pAq, gAq);
    cudaGetSymbolAddress((void**)&pAk, gAk);
    cudaGetSymbolAddress((void**)&pAv, gAv);
    cudaGetSymbolAddress((void**)&pRq, gRq);
    cudaGetSymbolAddress((void**)&pRk, gRk);
    cudaGetSymbolAddress((void**)&pRv, gRv);
    cudaGetSymbolAddress((void**)&pTA, gTA);
    cudaGetSymbolAddress((void**)&pTR, gTR);
    cudaGetSymbolAddress((void**)&pWp, gWp);
    cudaGetSymbolAddress((void**)&pWp1, gWp1);
    cudaGetSymbolAddress((void**)&pInvA, gInvA);
    cudaGetSymbolAddress((void**)&pInvR, gInvR);

    cudaFuncSetAttribute(gemm_fused_kernel<1,3,2>, cudaFuncAttributeMaxDynamicSharedMemorySize, GEMM_SMEM3);
    cudaFuncSetAttribute(gemm_fused_kernel<0,1,2>, cudaFuncAttributeMaxDynamicSharedMemorySize, GEMM_SMEM0);
    cudaFuncSetAttribute(gemm_fused_kernel<2,1,2>, cudaFuncAttributeMaxDynamicSharedMemorySize, GEMM_SMEM0);
    cudaFuncSetAttribute(attn_mma_kernel, cudaFuncAttributeMaxDynamicSharedMemorySize, ATT_SMEM);

    // weight slot order: 0=W_lig_t 1=WQl 2=WKl 3=WVl 4=WOl | 5=W_res_t 6=WQr 7=WKr 8=WVr 9=WOr
    WIn win;
    win.w[0] = (const float*)d_in[2];
    win.w[1] = (const float*)d_in[4];
    win.w[2] = (const float*)d_in[5];
    win.w[3] = (const float*)d_in[6];
    win.w[4] = (const float*)d_in[7];
    win.w[5] = (const float*)d_in[3];
    win.w[6] = (const float*)d_in[8];
    win.w[7] = (const float*)d_in[9];
    win.w[8] = (const float*)d_in[10];
    win.w[9] = (const float*)d_in[11];

    const int aTiles = (nA + 127) / 128;
    const int rTiles = (nR + 127) / 128;
    const int totTiles = aTiles + rTiles;
    const int WSLOT3 = DD * DD * 2;
    const int WSLOT1 = DD * DD;

    fill_inv_kernel<<<256, 256>>>(lig, res);
    presplit_w_kernel<<<(10 * DD * DD + 255) / 256, 256>>>(win, pWp, pWp1);

    // init transforms (3x, NT=2): A0 = leaky(fatoms@W_lig_t), R0 = leaky(fres@W_res_t)
    GArgs gi = {};
    gi.X[0] = fatoms; gi.X[1] = fres;
    gi.Wp[0][0] = pWp + 0 * WSLOT3; gi.Wp[1][0] = pWp + 5 * WSLOT3;
    gi.C[0][0] = pA; gi.C[1][0] = pR;
    gi.Ct[0] = pAt; gi.Ct[1] = pRt;
    gi.M[0] = nA; gi.M[1] = nR; gi.aTiles = aTiles;

    // fused QKV projections (1x, NT=2, pre-rounded X, rounded outputs)
    GArgs gq = {};
    gq.X[0] = pAt; gq.X[1] = pRt;
    for (int j = 0; j < 3; j++) {
        gq.Wp[0][j] = pWp1 + (1 + j) * WSLOT1;
        gq.Wp[1][j] = pWp1 + (6 + j) * WSLOT1;
    }
    gq.C[0][0] = pAq; gq.C[0][1] = pAk; gq.C[0][2] = pAv;
    gq.C[1][0] = pRq; gq.C[1][1] = pRk; gq.C[1][2] = pRv;
    gq.M[0] = nA; gq.M[1] = nR; gq.aTiles = aTiles;

    // output GEMMs (1x, NT=2): A = leaky(TA@WOl)*invA + A ; R = leaky(TR@WOr)*invR + R
    GArgs go = {};
    go.X[0] = pTA; go.X[1] = pTR;          // already tf32-rounded by attention store
    go.Wp[0][0] = pWp1 + 4 * WSLOT1; go.Wp[1][0] = pWp1 + 9 * WSLOT1;
    go.C[0][0] = pA; go.C[1][0] = pR;
    go.Ct[0] = pAt; go.Ct[1] = pRt;
    go.scale[0] = pInvA; go.scale[1] = pInvR;
    go.base[0] = pA; go.base[1] = pR;
    go.M[0] = nA; go.M[1] = nR; go.aTiles = aTiles;

    // final-iteration output GEMM writes directly into d_out (concat layout)
    GArgs gf = go;
    gf.C[0][0] = (float*)d_out;
    gf.C[1][0] = (float*)d_out + (size_t)nA * DD;

    // merged attention: role 0 = atoms->residues, role 1 = residues->atoms
    AArgs aa = {};
    aa.Q[0] = pAq; aa.K[0] = pRk; aa.V[0] = pRv; aa.O[0] = pTA;
    aa.scQ[0] = lig; aa.scKV[0] = res;
    aa.Q[1] = pRq; aa.K[1] = pAk; aa.V[1] = pAv; aa.O[1] = pTR;
    aa.scQ[1] = res; aa.scKV[1] = lig;

    gemm_fused_kernel<1,3,2><<<dim3(2, totTiles), 256, GEMM_SMEM3>>>(gi);

    for (int it = 0; it < 3; it++) {
        gemm_fused_kernel<0,1,2><<<dim3(6, totTiles), 256, GEMM_SMEM0>>>(gq);

        attn_mma_kernel<<<dim3(256, 9), 256, ATT_SMEM>>>(aa);

        gemm_fused_kernel<2,1,2><<<dim3(2, totTiles), 256, GEMM_SMEM0>>>(it == 2 ? gf : go);
    }
}